// round 12
// baseline (speedup 1.0000x reference)
#include <cuda_runtime.h>
#include <cuda_fp16.h>
#include <math.h>
#include <stdint.h>

// ---------------- problem constants ----------------
#define B_     4
#define T_     16
#define D_     512
#define S_     576
#define NSEQ_  2304            // B_*S_
#define M_     36864           // T_*NSEQ_
#define NH_    8
#define HD_    64
#define DQ_    128
#define GAMMA_ 0.1f

// ---------------- scratch ----------------
__device__ __half g_Qh [(size_t)M_*D_];
__device__ __half g_Kh [(size_t)M_*D_];
__device__ __half g_Vh [(size_t)M_*D_];
__device__ float  g_PV [M_];

__device__ __half g_AOpt[(size_t)M_*D_];
__device__ __half g_ASar[(size_t)M_*D_];
__device__ __half g_AOf [(size_t)M_*D_];
// transposed weights, n-major [n][k], k=512, single fp16 term
#define WOFF_Q  0
#define WOFF_K  (512*512)
#define WOFF_V  (2*512*512)
#define WOFF_O  (3*512*512)
#define WOFF_P1 (4*512*512)
__device__ __half g_Wth[4*512*512 + 128*512];

// ---------------- helpers ----------------
__device__ __forceinline__ uint32_t smem_cast(const void* p) {
    uint32_t a;
    asm("{ .reg .u64 t; cvta.to.shared.u64 t, %1; cvt.u32.u64 %0, t; }" : "=r"(a) : "l"(p));
    return a;
}

#define CP16(d, s) \
    asm volatile("cp.async.cg.shared.global [%0], [%1], 16;" :: "r"(d), "l"(s) : "memory")
#define CP_COMMIT()  asm volatile("cp.async.commit_group;" ::: "memory")
#define CP_WAIT2()   asm volatile("cp.async.wait_group 2;"  ::: "memory")
#define CP_WAITALL() asm volatile("cp.async.wait_all;"      ::: "memory")

#define LDSM4(r, a) \
    asm volatile("ldmatrix.sync.aligned.m8n8.x4.shared.b16 {%0,%1,%2,%3}, [%4];" \
        : "=r"((r)[0]), "=r"((r)[1]), "=r"((r)[2]), "=r"((r)[3]) : "r"(a))
#define LDSM4T(r, a) \
    asm volatile("ldmatrix.sync.aligned.m8n8.x4.trans.shared.b16 {%0,%1,%2,%3}, [%4];" \
        : "=r"((r)[0]), "=r"((r)[1]), "=r"((r)[2]), "=r"((r)[3]) : "r"(a))

__device__ __forceinline__ void mma16816(float c[4], const uint32_t a[4],
                                         uint32_t b0, uint32_t b1) {
    asm volatile(
        "mma.sync.aligned.m16n8k16.row.col.f32.f16.f16.f32 "
        "{%0,%1,%2,%3}, {%4,%5,%6,%7}, {%8,%9}, {%0,%1,%2,%3};"
        : "+f"(c[0]), "+f"(c[1]), "+f"(c[2]), "+f"(c[3])
        : "r"(a[0]), "r"(a[1]), "r"(a[2]), "r"(a[3]), "r"(b0), "r"(b1));
}

__device__ __forceinline__ uint32_t pack_h2(float a, float b) {
    __half2 t = __floats2half2_rn(a, b);
    return *reinterpret_cast<uint32_t*>(&t);
}

// ===========================================================================
// Prepass 1: weight transpose, single fp16 term. W[k][n] f32 -> [n][k] fp16.
// ===========================================================================
__global__ __launch_bounds__(256) void wsplit1_kernel(
    const float* __restrict__ W, int ncols, __half* __restrict__ oh)
{
    __shared__ float tile[32][33];
    const int n0 = blockIdx.x * 32, k0 = blockIdx.y * 32;
    const int tx = threadIdx.x & 31, ty = threadIdx.x >> 5;
    #pragma unroll
    for (int p = 0; p < 4; p++)
        tile[ty + p * 8][tx] = W[(size_t)(k0 + ty + p * 8) * ncols + n0 + tx];
    __syncthreads();
    #pragma unroll
    for (int p = 0; p < 4; p++) {
        const int row = ty + p * 8;
        oh[(size_t)(n0 + row) * 512 + k0 + tx] = __float2half_rn(tile[tx][row]);
    }
}

// ===========================================================================
// Prepass 2: merged gather, both inputs. z < 64: opt; z >= 64: sar.
// ===========================================================================
__global__ __launch_bounds__(256) void gsplit_kernel(
    const float* __restrict__ Aopt, const float* __restrict__ Asar,
    __half* __restrict__ Oopt, __half* __restrict__ Osar)
{
    __shared__ float tile[32][33];
    const int k0 = blockIdx.x * 32, sp0 = blockIdx.y * 32;
    int z = blockIdx.z;
    const float* Ain = (z < 64) ? Aopt : Asar;
    __half* oh = (z < 64) ? Oopt : Osar;
    z &= 63;
    const int b = z >> 4, t = z & 15;
    const int tx = threadIdx.x & 31, ty = threadIdx.x >> 5;
    const size_t base = ((size_t)(b * T_ + t) * D_) * S_;
    #pragma unroll
    for (int p = 0; p < 4; p++)
        tile[ty + p * 8][tx] = Ain[base + (size_t)(k0 + ty + p * 8) * S_ + sp0 + tx];
    __syncthreads();
    #pragma unroll
    for (int p = 0; p < 4; p++) {
        const int row = ty + p * 8;
        const int m = t * NSEQ_ + b * S_ + sp0 + row;
        oh[(size_t)m * 512 + k0 + tx] = __float2half_rn(tile[tx][row]);
    }
}

// ===========================================================================
// GEMM core (shared by all variants). BM=BN=128, 2 CTAs/SM, 4-stage cp.async.
// ===========================================================================
struct GemmCore {
    float acc[4][4][4];
};

__device__ __forceinline__ void gemm_mainloop(
    const __half* __restrict__ A, const __half* __restrict__ Bh,
    int m0, int j0, uint32_t sbase, int tid, float acc[4][4][4])
{
    constexpr int BM = 128, BN = 128;
    constexpr int OFF_BH = BM * 64;
    constexpr int STG = (BM + BN) * 64;

    const int lane = tid & 31;
    const int wid = tid >> 5;
    const int wm = wid >> 2, wn = wid & 3;

    #pragma unroll
    for (int i = 0; i < 4; i++)
        #pragma unroll
        for (int j = 0; j < 4; j++)
            #pragma unroll
            for (int q = 0; q < 4; q++) acc[i][j][q] = 0.f;

    auto issue = [&](int kt) {
        const int s = kt & 3;
        const int k0 = kt * 32;
        const uint32_t d0 = sbase + s * STG;
        #pragma unroll
        for (int idx = tid; idx < (BM + BN) * 4; idx += 256) {
            const int row = idx >> 2, c = idx & 3;
            if (row < BM) {
                const uint32_t d = d0 + ((row * 4 + (c ^ (row & 3))) << 4);
                CP16(d, A + (size_t)(m0 + row) * 512 + k0 + c * 8);
            } else {
                const int br = row - BM;
                const uint32_t d = d0 + OFF_BH + ((br * 4 + (c ^ (br & 3))) << 4);
                CP16(d, Bh + (size_t)(j0 + br) * 512 + k0 + c * 8);
            }
        }
    };

    issue(0); CP_COMMIT();
    issue(1); CP_COMMIT();
    issue(2); CP_COMMIT();

    #pragma unroll 1
    for (int kt = 0; kt < 16; kt++) {
        CP_WAIT2();
        __syncthreads();
        if (kt + 3 < 16) issue(kt + 3);
        CP_COMMIT();

        const int s = kt & 3;
        const uint32_t sa   = sbase + s * STG;
        const uint32_t sb_h = sa + OFF_BH;

        #pragma unroll
        for (int ks = 0; ks < 2; ks++) {
            uint32_t fa[4][4], fbh[2][4];
            #pragma unroll
            for (int i = 0; i < 4; i++) {
                const int row = wm * 64 + i * 16 + (lane & 15);
                const int c = ks * 2 + (lane >> 4);
                const uint32_t off = (uint32_t)((row * 4 + (c ^ (row & 3))) << 4);
                LDSM4(fa[i], sa + off);
            }
            #pragma unroll
            for (int jb = 0; jb < 2; jb++) {
                const int row = wn * 32 + jb * 16 + (lane & 15);
                const int c = ks * 2 + (lane >> 4);
                const uint32_t off = (uint32_t)((row * 4 + (c ^ (row & 3))) << 4);
                LDSM4(fbh[jb], sb_h + off);
            }
            #pragma unroll
            for (int i = 0; i < 4; i++)
                #pragma unroll
                for (int j = 0; j < 4; j++) {
                    const int jb = j >> 1, sel = j & 1;
                    mma16816(acc[i][j], fa[i], fbh[jb][sel], fbh[jb][sel + 2]);
                }
        }
    }
}

// ===========================================================================
// Uber QKV GEMM: blockIdx.z in {0,1,2} selects {Q, K, V}. Half output.
// ===========================================================================
__global__ __launch_bounds__(256, 2) void gemm_qkv(
    const __half* __restrict__ Aopt, const __half* __restrict__ Asar,
    const __half* __restrict__ Wth,
    const float* __restrict__ bq, const float* __restrict__ bk,
    const float* __restrict__ bv,
    __half* __restrict__ Qh, __half* __restrict__ Kh, __half* __restrict__ Vh)
{
    extern __shared__ char smraw[];
    const uint32_t sbase = smem_cast(smraw);
    const int tid = threadIdx.x;
    const int m0 = blockIdx.y * 128, j0 = blockIdx.x * 128;
    const int z = blockIdx.z;

    const __half* A  = (z == 0) ? Aopt : Asar;
    const __half* Bh = Wth + ((z == 0) ? WOFF_Q : (z == 1) ? WOFF_K : WOFF_V);
    const float* bias = (z == 0) ? bq : (z == 1) ? bk : bv;
    __half* Ch = (z == 0) ? Qh : (z == 1) ? Kh : Vh;

    float acc[4][4][4];
    gemm_mainloop(A, Bh, m0, j0, sbase, tid, acc);

    const int lane = tid & 31, wid = tid >> 5;
    const int wm = wid >> 2, wn = wid & 3;
    const int gid = lane >> 2, tig = lane & 3;
    #pragma unroll
    for (int i = 0; i < 4; i++) {
        const int row0 = m0 + wm * 64 + i * 16 + gid;
        #pragma unroll
        for (int j = 0; j < 4; j++) {
            const int col = j0 + wn * 32 + j * 8 + tig * 2;
            const float b0 = __ldg(bias + col), b1 = __ldg(bias + col + 1);
            *reinterpret_cast<__half2*>(Ch + (size_t)row0 * D_ + col)
                = __floats2half2_rn(acc[i][j][0] + b0, acc[i][j][1] + b1);
            *reinterpret_cast<__half2*>(Ch + (size_t)(row0 + 8) * D_ + col)
                = __floats2half2_rn(acc[i][j][2] + b0, acc[i][j][3] + b1);
        }
    }
}

// ===========================================================================
// MLP GEMM: gelu -> dot(Wp2) -> reduce -> sigmoid -> g_PV. grid (1, 288).
// ===========================================================================
__global__ __launch_bounds__(256, 2) void gemm_mlp(
    const __half* __restrict__ A, const __half* __restrict__ Bh,
    const float* __restrict__ bias,
    const float* __restrict__ Wp2, const float* __restrict__ bp2)
{
    extern __shared__ char smraw[];
    const uint32_t sbase = smem_cast(smraw);
    const int tid = threadIdx.x;
    const int m0 = blockIdx.y * 128;

    float acc[4][4][4];
    gemm_mainloop(A, Bh, m0, 0, sbase, tid, acc);

    const int lane = tid & 31, wid = tid >> 5;
    const int wm = wid >> 2, wn = wid & 3;
    const int gid = lane >> 2, tig = lane & 3;

    CP_WAITALL();
    __syncthreads();
    float* red = reinterpret_cast<float*>(smraw);   // [4 wn][128 rows]
    #pragma unroll
    for (int i = 0; i < 4; i++) {
        const int r0 = wm * 64 + i * 16 + gid;
        float p0 = 0.f, p1 = 0.f;
        #pragma unroll
        for (int j = 0; j < 4; j++) {
            const int col = wn * 32 + j * 8 + tig * 2;
            const float b0 = __ldg(bias + col), b1 = __ldg(bias + col + 1);
            const float w0 = __ldg(Wp2 + col),  w1 = __ldg(Wp2 + col + 1);
            float v0 = acc[i][j][0] + b0; v0 *= normcdff(v0);
            float v1 = acc[i][j][1] + b1; v1 *= normcdff(v1);
            float v2 = acc[i][j][2] + b0; v2 *= normcdff(v2);
            float v3 = acc[i][j][3] + b1; v3 *= normcdff(v3);
            p0 += v0 * w0 + v1 * w1;
            p1 += v2 * w0 + v3 * w1;
        }
        p0 += __shfl_xor_sync(0xFFFFFFFFu, p0, 1);
        p0 += __shfl_xor_sync(0xFFFFFFFFu, p0, 2);
        p1 += __shfl_xor_sync(0xFFFFFFFFu, p1, 1);
        p1 += __shfl_xor_sync(0xFFFFFFFFu, p1, 2);
        if (tig == 0) {
            red[wn * 128 + r0]     = p0;
            red[wn * 128 + r0 + 8] = p1;
        }
    }
    __syncthreads();
    if (tid < 128) {
        float x = red[tid] + red[128 + tid] + red[256 + tid] + red[384 + tid] + bp2[0];
        g_PV[m0 + tid] = 1.f / (1.f + expf(-x));
    }
}

// ===========================================================================
// Output GEMM with fused scatter into 5D (B,T,D,24,24) float out.
// ===========================================================================
__global__ __launch_bounds__(256, 2) void gemm_out(
    const __half* __restrict__ A, const __half* __restrict__ Bh,
    const float* __restrict__ bias, float* __restrict__ Cf)
{
    extern __shared__ char smraw[];
    const uint32_t sbase = smem_cast(smraw);
    const int tid = threadIdx.x;
    const int m0 = blockIdx.y * 128, j0 = blockIdx.x * 128;

    float acc[4][4][4];
    gemm_mainloop(A, Bh, m0, j0, sbase, tid, acc);

    const int lane = tid & 31, wid = tid >> 5;
    const int wm = wid >> 2, wn = wid & 3;
    const int gid = lane >> 2, tig = lane & 3;

    CP_WAITALL();
    __syncthreads();
    float* Csm = reinterpret_cast<float*>(smraw);   // [128][132]
    #pragma unroll
    for (int i = 0; i < 4; i++) {
        const int row0 = wm * 64 + i * 16 + gid;
        #pragma unroll
        for (int j = 0; j < 4; j++) {
            const int col = wn * 32 + j * 8 + tig * 2;
            const float b0 = __ldg(bias + j0 + col), b1 = __ldg(bias + j0 + col + 1);
            Csm[(col)     * 132 + row0]     = acc[i][j][0] + b0;
            Csm[(col + 1) * 132 + row0]     = acc[i][j][1] + b1;
            Csm[(col)     * 132 + row0 + 8] = acc[i][j][2] + b0;
            Csm[(col + 1) * 132 + row0 + 8] = acc[i][j][3] + b1;
        }
    }
    __syncthreads();
    const int t  = m0 / NSEQ_;
    const int n0 = m0 % NSEQ_;
    #pragma unroll 4
    for (int idx = tid; idx < 128 * 128; idx += 256) {
        const int j = idx >> 7, mr = idx & 127;
        const int n = n0 + mr;
        const int b = n / S_, sp = n % S_;
        Cf[((size_t)((b * T_ + t) * D_) + j0 + j) * S_ + sp] = Csm[j * 132 + mr];
    }
}

// ===========================================================================
// Attention (mma.sync): one block per n (256 thr, warp = head).
// ===========================================================================
#define ATT_STRIDE 520
#define ATT_SMEM   (3 * 16 * ATT_STRIDE * 2 + 64)

__global__ __launch_bounds__(256) void attn_kernel()
{
    extern __shared__ char araw[];
    __half* Qs = reinterpret_cast<__half*>(araw);
    __half* Ks = Qs + 16 * ATT_STRIDE;
    __half* Vs = Ks + 16 * ATT_STRIDE;
    float*  Pv = reinterpret_cast<float*>(Vs + 16 * ATT_STRIDE);

    const int n = blockIdx.x;
    const int tid = threadIdx.x;
    const int lane = tid & 31, w = tid >> 5;
    const int gid = lane >> 2, tig = lane & 3;
    const int lrow = lane & 15, lchunk = lane >> 4;

    #pragma unroll
    for (int i = 0; i < 4; i++) {
        int idx = tid + i * 256;
        int t = idx >> 6, c = (idx & 63) * 8;
        size_t src = ((size_t)(t * NSEQ_ + n)) * D_ + c;
        *reinterpret_cast<float4*>(Qs + t * ATT_STRIDE + c) =
            *reinterpret_cast<const float4*>(g_Qh + src);
        *reinterpret_cast<float4*>(Ks + t * ATT_STRIDE + c) =
            *reinterpret_cast<const float4*>(g_Kh + src);
        *reinterpret_cast<float4*>(Vs + t * ATT_STRIDE + c) =
            *reinterpret_cast<const float4*>(g_Vh + src);
    }
    if (tid < 16) Pv[tid] = g_PV[tid * NSEQ_ + n];
    __syncthreads();

    const int hc = w * HD_;

    float s0[4] = {0.f, 0.f, 0.f, 0.f}, s1[4] = {0.f, 0.f, 0.f, 0.f};
    #pragma unroll
    for (int kk = 0; kk < 4; kk++) {
        uint32_t fq[4], fk[4];
        LDSM4(fq, smem_cast(Qs + lrow * ATT_STRIDE + hc + kk * 16 + lchunk * 8));
        LDSM4(fk, smem_cast(Ks + lrow * ATT_STRIDE + hc + kk * 16 + lchunk * 8));
        mma16816(s0, fq, fk[0], fk[2]);
        mma16816(s1, fq, fk[1], fk[3]);
    }

    const float pA0 = Pv[tig * 2],     pA1 = Pv[tig * 2 + 1];
    const float pB0 = Pv[8 + tig * 2], pB1 = Pv[8 + tig * 2 + 1];
    s0[0] = s0[0] * 0.125f - GAMMA_ * pA0;
    s0[1] = s0[1] * 0.125f - GAMMA_ * pA1;
    s0[2] = s0[2] * 0.125f - GAMMA_ * pA0;
    s0[3] = s0[3] * 0.125f - GAMMA_ * pA1;
    s1[0] = s1[0] * 0.125f - GAMMA_ * pB0;
    s1[1] = s1[1] * 0.125f - GAMMA_ * pB1;
    s1[2] = s1[2] * 0.125f - GAMMA_ * pB0;
    s1[3] = s1[3] * 0.125f - GAMMA_ * pB1;

    float mA = fmaxf(fmaxf(s0[0], s0[1]), fmaxf(s1[0], s1[1]));
    float mB = fmaxf(fmaxf(s0[2], s0[3]), fmaxf(s1[2], s1[3]));
    mA = fmaxf(mA, __shfl_xor_sync(0xFFFFFFFFu, mA, 1));
    mA = fmaxf(mA, __shfl_xor_sync(0xFFFFFFFFu, mA, 2));
    mB = fmaxf(mB, __shfl_xor_sync(0xFFFFFFFFu, mB, 1));
    mB = fmaxf(mB, __shfl_xor_sync(0xFFFFFFFFu, mB, 2));
    s0[0] = expf(s0[0] - mA); s0[1] = expf(s0[1] - mA);
    s1[0] = expf(s1[0] - mA); s1[1] = expf(s1[1] - mA);
    s0[2] = expf(s0[2] - mB); s0[3] = expf(s0[3] - mB);
    s1[2] = expf(s1[2] - mB); s1[3] = expf(s1[3] - mB);
    float sumA = s0[0] + s0[1] + s1[0] + s1[1];
    float sumB = s0[2] + s0[3] + s1[2] + s1[3];
    sumA += __shfl_xor_sync(0xFFFFFFFFu, sumA, 1);
    sumA += __shfl_xor_sync(0xFFFFFFFFu, sumA, 2);
    sumB += __shfl_xor_sync(0xFFFFFFFFu, sumB, 1);
    sumB += __shfl_xor_sync(0xFFFFFFFFu, sumB, 2);
    const float invA = 1.f / sumA, invB = 1.f / sumB;

    uint32_t fa[4];
    fa[0] = pack_h2(s0[0] * invA, s0[1] * invA);
    fa[1] = pack_h2(s0[2] * invB, s0[3] * invB);
    fa[2] = pack_h2(s1[0] * invA, s1[1] * invA);
    fa[3] = pack_h2(s1[2] * invB, s1[3] * invB);

    const size_t r0 = ((size_t)(gid * NSEQ_ + n)) * D_;
    const size_t r1 = ((size_t)((gid + 8) * NSEQ_ + n)) * D_;
    #pragma unroll
    for (int eb = 0; eb < 4; eb++) {
        uint32_t fv[4];
        LDSM4T(fv, smem_cast(Vs + lrow * ATT_STRIDE + hc + eb * 16 + lchunk * 8));
        float o0[4] = {0.f, 0.f, 0.f, 0.f}, o1[4] = {0.f, 0.f, 0.f, 0.f};
        mma16816(o0, fa, fv[0], fv[1]);
        mma16816(o1, fa, fv[2], fv[3]);
        const int e0 = hc + eb * 16 + tig * 2;
        const int e1 = e0 + 8;
        *reinterpret_cast<__half2*>(g_AOf + r0 + e0) = __floats2half2_rn(o0[0], o0[1]);
        *reinterpret_cast<__half2*>(g_AOf + r1 + e0) = __floats2half2_rn(o0[2], o0[3]);
        *reinterpret_cast<__half2*>(g_AOf + r0 + e1) = __floats2half2_rn(o1[0], o1[1]);
        *reinterpret_cast<__half2*>(g_AOf + r1 + e1) = __floats2half2_rn(o1[2], o1[3]);
    }
}

// ---------------------------------------------------------------------------
extern "C" void kernel_launch(void* const* d_in, const int* in_sizes, int n_in,
                              void* d_out, int out_size)
{
    const float* h_opt = (const float*)d_in[0];
    const float* h_sar = (const float*)d_in[1];
    const float* Wq  = (const float*)d_in[2];  const float* bq  = (const float*)d_in[3];
    const float* Wk  = (const float*)d_in[4];  const float* bk  = (const float*)d_in[5];
    const float* Wv  = (const float*)d_in[6];  const float* bv  = (const float*)d_in[7];
    const float* Wo  = (const float*)d_in[8];  const float* bo  = (const float*)d_in[9];
    const float* Wp1 = (const float*)d_in[10]; const float* bp1 = (const float*)d_in[11];
    const float* Wp2 = (const float*)d_in[12]; const float* bp2 = (const float*)d_in[13];
    float* out = (float*)d_out;

    void *pQ, *pK, *pV, *pAO, *pAS, *pAOf, *pWh;
    cudaGetSymbolAddress(&pQ,  g_Qh);
    cudaGetSymbolAddress(&pK,  g_Kh);
    cudaGetSymbolAddress(&pV,  g_Vh);
    cudaGetSymbolAddress(&pAO, g_AOpt);
    cudaGetSymbolAddress(&pAS, g_ASar);
    cudaGetSymbolAddress(&pAOf, g_AOf);
    cudaGetSymbolAddress(&pWh, g_Wth);

    __half* Wth = (__half*)pWh;

    constexpr int SM_PIPE = 4 * (128 + 128) * 64;   // 65536
    constexpr int SM_SCAT = 128 * 132 * 4;          // 67584
    cudaFuncSetAttribute(gemm_qkv, cudaFuncAttributeMaxDynamicSharedMemorySize, SM_PIPE);
    cudaFuncSetAttribute(gemm_mlp, cudaFuncAttributeMaxDynamicSharedMemorySize, SM_PIPE);
    cudaFuncSetAttribute(gemm_out, cudaFuncAttributeMaxDynamicSharedMemorySize, SM_SCAT);
    cudaFuncSetAttribute(attn_kernel, cudaFuncAttributeMaxDynamicSharedMemorySize, ATT_SMEM);

    static cudaStream_t s1 = nullptr;
    static cudaEvent_t evRoot = nullptr, evG = nullptr, evW = nullptr, evM = nullptr;
    if (s1 == nullptr) {
        cudaStreamCreateWithFlags(&s1, cudaStreamNonBlocking);
        cudaEventCreateWithFlags(&evRoot, cudaEventDisableTiming);
        cudaEventCreateWithFlags(&evG,    cudaEventDisableTiming);
        cudaEventCreateWithFlags(&evW,    cudaEventDisableTiming);
        cudaEventCreateWithFlags(&evM,    cudaEventDisableTiming);
    }

    dim3 blk(256);
    cudaStream_t s0 = 0;

    cudaEventRecord(evRoot, s0);
    cudaStreamWaitEvent(s1, evRoot, 0);

    // S0: merged gather (opt + sar)
    gsplit_kernel<<<dim3(16, 18, 128), blk, 0, s0>>>(h_opt, h_sar,
        (__half*)pAO, (__half*)pAS);
    cudaEventRecord(evG, s0);

    // S1: all weight transposes (concurrent with gather), then MLP GEMM
    wsplit1_kernel<<<dim3(16, 16), blk, 0, s1>>>(Wq, 512, Wth + WOFF_Q);
    wsplit1_kernel<<<dim3(16, 16), blk, 0, s1>>>(Wk, 512, Wth + WOFF_K);
    wsplit1_kernel<<<dim3(16, 16), blk, 0, s1>>>(Wv, 512, Wth + WOFF_V);
    cudaEventRecord(evW, s1);
    wsplit1_kernel<<<dim3(4, 16), blk, 0, s1>>>(Wp1, 128, Wth + WOFF_P1);
    wsplit1_kernel<<<dim3(16, 16), blk, 0, s1>>>(Wo, 512, Wth + WOFF_O);
    cudaStreamWaitEvent(s1, evG, 0);
    gemm_mlp<<<dim3(1, 288), blk, SM_PIPE, s1>>>((__half*)pAS, Wth + WOFF_P1,
        bp1, Wp2, bp2);
    cudaEventRecord(evM, s1);

    // S0: uber QKV GEMM (waits on QKV weights)
    cudaStreamWaitEvent(s0, evW, 0);
    gemm_qkv<<<dim3(4, 288, 3), blk, SM_PIPE, s0>>>((__half*)pAO, (__half*)pAS, Wth,
        bq, bk, bv, (__half*)pQ, (__half*)pK, (__half*)pV);

    // join: attention needs QKV (s0) and PV (s1)
    cudaStreamWaitEvent(s0, evM, 0);
    attn_kernel<<<NSEQ_, 256, ATT_SMEM, s0>>>();

    // output projection + fused scatter (Wo ready via evM ordering on s1)
    gemm_out<<<dim3(4, 288), blk, SM_SCAT, s0>>>((__half*)pAOf, Wth + WOFF_O, bo, out);
}

// round 13
// speedup vs baseline: 1.0016x; 1.0016x over previous
#include <cuda_runtime.h>
#include <cuda_fp16.h>
#include <math.h>
#include <stdint.h>

// ---------------- problem constants ----------------
#define B_     4
#define T_     16
#define D_     512
#define S_     576
#define NSEQ_  2304            // B_*S_
#define M_     36864           // T_*NSEQ_
#define NH_    8
#define HD_    64
#define DQ_    128
#define GAMMA_ 0.1f

// ---------------- scratch ----------------
__device__ __half g_Qh [(size_t)M_*D_];
__device__ __half g_Kh [(size_t)M_*D_];
__device__ __half g_Vh [(size_t)M_*D_];
__device__ float  g_PV [M_];

__device__ __half g_AOpt[(size_t)M_*D_];
__device__ __half g_ASar[(size_t)M_*D_];
__device__ __half g_AOf [(size_t)M_*D_];
// transposed weights, n-major [n][k], k=512, single fp16 term
#define WOFF_Q  0
#define WOFF_K  (512*512)
#define WOFF_V  (2*512*512)
#define WOFF_O  (3*512*512)
#define WOFF_P1 (4*512*512)
__device__ __half g_Wth[4*512*512 + 128*512];

// ---------------- helpers ----------------
__device__ __forceinline__ uint32_t smem_cast(const void* p) {
    uint32_t a;
    asm("{ .reg .u64 t; cvta.to.shared.u64 t, %1; cvt.u32.u64 %0, t; }" : "=r"(a) : "l"(p));
    return a;
}

#define CP16(d, s) \
    asm volatile("cp.async.cg.shared.global [%0], [%1], 16;" :: "r"(d), "l"(s) : "memory")
#define CP_COMMIT()  asm volatile("cp.async.commit_group;" ::: "memory")
#define CP_WAIT2()   asm volatile("cp.async.wait_group 2;"  ::: "memory")
#define CP_WAITALL() asm volatile("cp.async.wait_all;"      ::: "memory")

#define LDSM4(r, a) \
    asm volatile("ldmatrix.sync.aligned.m8n8.x4.shared.b16 {%0,%1,%2,%3}, [%4];" \
        : "=r"((r)[0]), "=r"((r)[1]), "=r"((r)[2]), "=r"((r)[3]) : "r"(a))
#define LDSM4T(r, a) \
    asm volatile("ldmatrix.sync.aligned.m8n8.x4.trans.shared.b16 {%0,%1,%2,%3}, [%4];" \
        : "=r"((r)[0]), "=r"((r)[1]), "=r"((r)[2]), "=r"((r)[3]) : "r"(a))

__device__ __forceinline__ void mma16816(float c[4], const uint32_t a[4],
                                         uint32_t b0, uint32_t b1) {
    asm volatile(
        "mma.sync.aligned.m16n8k16.row.col.f32.f16.f16.f32 "
        "{%0,%1,%2,%3}, {%4,%5,%6,%7}, {%8,%9}, {%0,%1,%2,%3};"
        : "+f"(c[0]), "+f"(c[1]), "+f"(c[2]), "+f"(c[3])
        : "r"(a[0]), "r"(a[1]), "r"(a[2]), "r"(a[3]), "r"(b0), "r"(b1));
}

__device__ __forceinline__ uint32_t pack_h2(float a, float b) {
    __half2 t = __floats2half2_rn(a, b);
    return *reinterpret_cast<uint32_t*>(&t);
}

// ===========================================================================
// Prepass 1: weight transpose, single fp16 term. W[k][n] f32 -> [n][k] fp16.
// ===========================================================================
__global__ __launch_bounds__(256) void wsplit1_kernel(
    const float* __restrict__ W, int ncols, __half* __restrict__ oh)
{
    __shared__ float tile[32][33];
    const int n0 = blockIdx.x * 32, k0 = blockIdx.y * 32;
    const int tx = threadIdx.x & 31, ty = threadIdx.x >> 5;
    #pragma unroll
    for (int p = 0; p < 4; p++)
        tile[ty + p * 8][tx] = W[(size_t)(k0 + ty + p * 8) * ncols + n0 + tx];
    __syncthreads();
    #pragma unroll
    for (int p = 0; p < 4; p++) {
        const int row = ty + p * 8;
        oh[(size_t)(n0 + row) * 512 + k0 + tx] = __float2half_rn(tile[tx][row]);
    }
}

// ===========================================================================
// Prepass 2: merged gather, both inputs. z < 64: opt; z >= 64: sar.
// half2-vectorized output writes.
// ===========================================================================
__global__ __launch_bounds__(256) void gsplit_kernel(
    const float* __restrict__ Aopt, const float* __restrict__ Asar,
    __half* __restrict__ Oopt, __half* __restrict__ Osar)
{
    __shared__ float tile[32][33];   // [k][sp]
    const int k0 = blockIdx.x * 32, sp0 = blockIdx.y * 32;
    int z = blockIdx.z;
    const float* Ain = (z < 64) ? Aopt : Asar;
    __half* oh = (z < 64) ? Oopt : Osar;
    z &= 63;
    const int b = z >> 4, t = z & 15;
    const int tx = threadIdx.x & 31, ty = threadIdx.x >> 5;
    const size_t base = ((size_t)(b * T_ + t) * D_) * S_;
    #pragma unroll
    for (int p = 0; p < 4; p++)
        tile[ty + p * 8][tx] = Ain[base + (size_t)(k0 + ty + p * 8) * S_ + sp0 + tx];
    __syncthreads();
    const int mb = t * NSEQ_ + b * S_ + sp0;
    #pragma unroll
    for (int it = 0; it < 2; it++) {
        const int idx = threadIdx.x + it * 256;   // 0..511
        const int sp = idx >> 4, kp = idx & 15;
        __half2 h = __floats2half2_rn(tile[2 * kp][sp], tile[2 * kp + 1][sp]);
        *reinterpret_cast<__half2*>(oh + (size_t)(mb + sp) * 512 + k0 + 2 * kp) = h;
    }
}

// ===========================================================================
// GEMM core. BM=BN=128, 2 CTAs/SM, 4-stage cp.async, ldmatrix.
// ===========================================================================
__device__ __forceinline__ void gemm_mainloop(
    const __half* __restrict__ A, const __half* __restrict__ Bh,
    int m0, int j0, uint32_t sbase, int tid, float acc[4][4][4])
{
    constexpr int BM = 128, BN = 128;
    constexpr int OFF_BH = BM * 64;
    constexpr int STG = (BM + BN) * 64;

    const int lane = tid & 31;
    const int wid = tid >> 5;
    const int wm = wid >> 2, wn = wid & 3;

    #pragma unroll
    for (int i = 0; i < 4; i++)
        #pragma unroll
        for (int j = 0; j < 4; j++)
            #pragma unroll
            for (int q = 0; q < 4; q++) acc[i][j][q] = 0.f;

    auto issue = [&](int kt) {
        const int s = kt & 3;
        const int k0 = kt * 32;
        const uint32_t d0 = sbase + s * STG;
        #pragma unroll
        for (int idx = tid; idx < (BM + BN) * 4; idx += 256) {
            const int row = idx >> 2, c = idx & 3;
            if (row < BM) {
                const uint32_t d = d0 + ((row * 4 + (c ^ (row & 3))) << 4);
                CP16(d, A + (size_t)(m0 + row) * 512 + k0 + c * 8);
            } else {
                const int br = row - BM;
                const uint32_t d = d0 + OFF_BH + ((br * 4 + (c ^ (br & 3))) << 4);
                CP16(d, Bh + (size_t)(j0 + br) * 512 + k0 + c * 8);
            }
        }
    };

    issue(0); CP_COMMIT();
    issue(1); CP_COMMIT();
    issue(2); CP_COMMIT();

    #pragma unroll 1
    for (int kt = 0; kt < 16; kt++) {
        CP_WAIT2();
        __syncthreads();
        if (kt + 3 < 16) issue(kt + 3);
        CP_COMMIT();

        const int s = kt & 3;
        const uint32_t sa   = sbase + s * STG;
        const uint32_t sb_h = sa + OFF_BH;

        #pragma unroll
        for (int ks = 0; ks < 2; ks++) {
            uint32_t fa[4][4], fbh[2][4];
            #pragma unroll
            for (int i = 0; i < 4; i++) {
                const int row = wm * 64 + i * 16 + (lane & 15);
                const int c = ks * 2 + (lane >> 4);
                const uint32_t off = (uint32_t)((row * 4 + (c ^ (row & 3))) << 4);
                LDSM4(fa[i], sa + off);
            }
            #pragma unroll
            for (int jb = 0; jb < 2; jb++) {
                const int row = wn * 32 + jb * 16 + (lane & 15);
                const int c = ks * 2 + (lane >> 4);
                const uint32_t off = (uint32_t)((row * 4 + (c ^ (row & 3))) << 4);
                LDSM4(fbh[jb], sb_h + off);
            }
            #pragma unroll
            for (int i = 0; i < 4; i++)
                #pragma unroll
                for (int j = 0; j < 4; j++) {
                    const int jb = j >> 1, sel = j & 1;
                    mma16816(acc[i][j], fa[i], fbh[jb][sel], fbh[jb][sel + 2]);
                }
        }
    }
}

// ===========================================================================
// Uber QKV GEMM: blockIdx.z in {0,1,2} selects {Q, K, V}. Half output.
// ===========================================================================
__global__ __launch_bounds__(256, 2) void gemm_qkv(
    const __half* __restrict__ Aopt, const __half* __restrict__ Asar,
    const __half* __restrict__ Wth,
    const float* __restrict__ bq, const float* __restrict__ bk,
    const float* __restrict__ bv,
    __half* __restrict__ Qh, __half* __restrict__ Kh, __half* __restrict__ Vh)
{
    extern __shared__ char smraw[];
    const uint32_t sbase = smem_cast(smraw);
    const int tid = threadIdx.x;
    const int m0 = blockIdx.y * 128, j0 = blockIdx.x * 128;
    const int z = blockIdx.z;

    const __half* A  = (z == 0) ? Aopt : Asar;
    const __half* Bh = Wth + ((z == 0) ? WOFF_Q : (z == 1) ? WOFF_K : WOFF_V);
    const float* bias = (z == 0) ? bq : (z == 1) ? bk : bv;
    __half* Ch = (z == 0) ? Qh : (z == 1) ? Kh : Vh;

    float acc[4][4][4];
    gemm_mainloop(A, Bh, m0, j0, sbase, tid, acc);

    const int lane = tid & 31, wid = tid >> 5;
    const int wm = wid >> 2, wn = wid & 3;
    const int gid = lane >> 2, tig = lane & 3;
    #pragma unroll
    for (int i = 0; i < 4; i++) {
        const int row0 = m0 + wm * 64 + i * 16 + gid;
        #pragma unroll
        for (int j = 0; j < 4; j++) {
            const int col = j0 + wn * 32 + j * 8 + tig * 2;
            const float b0 = __ldg(bias + col), b1 = __ldg(bias + col + 1);
            *reinterpret_cast<__half2*>(Ch + (size_t)row0 * D_ + col)
                = __floats2half2_rn(acc[i][j][0] + b0, acc[i][j][1] + b1);
            *reinterpret_cast<__half2*>(Ch + (size_t)(row0 + 8) * D_ + col)
                = __floats2half2_rn(acc[i][j][2] + b0, acc[i][j][3] + b1);
        }
    }
}

// ===========================================================================
// MLP GEMM: gelu -> dot(Wp2) -> reduce -> sigmoid -> g_PV. grid (1, 288).
// ===========================================================================
__global__ __launch_bounds__(256, 2) void gemm_mlp(
    const __half* __restrict__ A, const __half* __restrict__ Bh,
    const float* __restrict__ bias,
    const float* __restrict__ Wp2, const float* __restrict__ bp2)
{
    extern __shared__ char smraw[];
    const uint32_t sbase = smem_cast(smraw);
    const int tid = threadIdx.x;
    const int m0 = blockIdx.y * 128;

    float acc[4][4][4];
    gemm_mainloop(A, Bh, m0, 0, sbase, tid, acc);

    const int lane = tid & 31, wid = tid >> 5;
    const int wm = wid >> 2, wn = wid & 3;
    const int gid = lane >> 2, tig = lane & 3;

    CP_WAITALL();
    __syncthreads();
    float* red = reinterpret_cast<float*>(smraw);   // [4 wn][128 rows]
    #pragma unroll
    for (int i = 0; i < 4; i++) {
        const int r0 = wm * 64 + i * 16 + gid;
        float p0 = 0.f, p1 = 0.f;
        #pragma unroll
        for (int j = 0; j < 4; j++) {
            const int col = wn * 32 + j * 8 + tig * 2;
            const float b0 = __ldg(bias + col), b1 = __ldg(bias + col + 1);
            const float w0 = __ldg(Wp2 + col),  w1 = __ldg(Wp2 + col + 1);
            float v0 = acc[i][j][0] + b0; v0 *= normcdff(v0);
            float v1 = acc[i][j][1] + b1; v1 *= normcdff(v1);
            float v2 = acc[i][j][2] + b0; v2 *= normcdff(v2);
            float v3 = acc[i][j][3] + b1; v3 *= normcdff(v3);
            p0 += v0 * w0 + v1 * w1;
            p1 += v2 * w0 + v3 * w1;
        }
        p0 += __shfl_xor_sync(0xFFFFFFFFu, p0, 1);
        p0 += __shfl_xor_sync(0xFFFFFFFFu, p0, 2);
        p1 += __shfl_xor_sync(0xFFFFFFFFu, p1, 1);
        p1 += __shfl_xor_sync(0xFFFFFFFFu, p1, 2);
        if (tig == 0) {
            red[wn * 128 + r0]     = p0;
            red[wn * 128 + r0 + 8] = p1;
        }
    }
    __syncthreads();
    if (tid < 128) {
        float x = red[tid] + red[128 + tid] + red[256 + tid] + red[384 + tid] + bp2[0];
        g_PV[m0 + tid] = 1.f / (1.f + expf(-x));
    }
}

// ===========================================================================
// Output GEMM half: y-remapped so a half covers n in [yoff*128, yoff*128+1152).
// y = (q/9)*18 + q%9 + yoff, q = blockIdx.y in [0,144). Fused 5D scatter.
// ===========================================================================
__global__ __launch_bounds__(256, 2) void gemm_out(
    const __half* __restrict__ A, const __half* __restrict__ Bh,
    const float* __restrict__ bias, float* __restrict__ Cf, int yoff)
{
    extern __shared__ char smraw[];
    const uint32_t sbase = smem_cast(smraw);
    const int tid = threadIdx.x;
    const int q = blockIdx.y;
    const int y = (q / 9) * 18 + (q % 9) + yoff;
    const int m0 = y * 128, j0 = blockIdx.x * 128;

    float acc[4][4][4];
    gemm_mainloop(A, Bh, m0, j0, sbase, tid, acc);

    const int lane = tid & 31, wid = tid >> 5;
    const int wm = wid >> 2, wn = wid & 3;
    const int gid = lane >> 2, tig = lane & 3;

    CP_WAITALL();
    __syncthreads();
    float* Csm = reinterpret_cast<float*>(smraw);   // [128][132]
    #pragma unroll
    for (int i = 0; i < 4; i++) {
        const int row0 = wm * 64 + i * 16 + gid;
        #pragma unroll
        for (int j = 0; j < 4; j++) {
            const int col = wn * 32 + j * 8 + tig * 2;
            const float b0 = __ldg(bias + j0 + col), b1 = __ldg(bias + j0 + col + 1);
            Csm[(col)     * 132 + row0]     = acc[i][j][0] + b0;
            Csm[(col + 1) * 132 + row0]     = acc[i][j][1] + b1;
            Csm[(col)     * 132 + row0 + 8] = acc[i][j][2] + b0;
            Csm[(col + 1) * 132 + row0 + 8] = acc[i][j][3] + b1;
        }
    }
    __syncthreads();
    const int t  = m0 / NSEQ_;
    const int n0 = m0 % NSEQ_;
    #pragma unroll 4
    for (int idx = tid; idx < 128 * 128; idx += 256) {
        const int j = idx >> 7, mr = idx & 127;
        const int n = n0 + mr;
        const int b = n / S_, sp = n % S_;
        Cf[((size_t)((b * T_ + t) * D_) + j0 + j) * S_ + sp] = Csm[j * 132 + mr];
    }
}

// ===========================================================================
// Attention (mma.sync): one block per n (256 thr, warp = head). noff offsets n.
// ===========================================================================
#define ATT_STRIDE 520
#define ATT_SMEM   (3 * 16 * ATT_STRIDE * 2 + 64)

__global__ __launch_bounds__(256) void attn_kernel(int noff)
{
    extern __shared__ char araw[];
    __half* Qs = reinterpret_cast<__half*>(araw);
    __half* Ks = Qs + 16 * ATT_STRIDE;
    __half* Vs = Ks + 16 * ATT_STRIDE;
    float*  Pv = reinterpret_cast<float*>(Vs + 16 * ATT_STRIDE);

    const int n = blockIdx.x + noff;
    const int tid = threadIdx.x;
    const int lane = tid & 31, w = tid >> 5;
    const int gid = lane >> 2, tig = lane & 3;
    const int lrow = lane & 15, lchunk = lane >> 4;

    #pragma unroll
    for (int i = 0; i < 4; i++) {
        int idx = tid + i * 256;
        int t = idx >> 6, c = (idx & 63) * 8;
        size_t src = ((size_t)(t * NSEQ_ + n)) * D_ + c;
        *reinterpret_cast<float4*>(Qs + t * ATT_STRIDE + c) =
            *reinterpret_cast<const float4*>(g_Qh + src);
        *reinterpret_cast<float4*>(Ks + t * ATT_STRIDE + c) =
            *reinterpret_cast<const float4*>(g_Kh + src);
        *reinterpret_cast<float4*>(Vs + t * ATT_STRIDE + c) =
            *reinterpret_cast<const float4*>(g_Vh + src);
    }
    if (tid < 16) Pv[tid] = g_PV[tid * NSEQ_ + n];
    __syncthreads();

    const int hc = w * HD_;

    float s0[4] = {0.f, 0.f, 0.f, 0.f}, s1[4] = {0.f, 0.f, 0.f, 0.f};
    #pragma unroll
    for (int kk = 0; kk < 4; kk++) {
        uint32_t fq[4], fk[4];
        LDSM4(fq, smem_cast(Qs + lrow * ATT_STRIDE + hc + kk * 16 + lchunk * 8));
        LDSM4(fk, smem_cast(Ks + lrow * ATT_STRIDE + hc + kk * 16 + lchunk * 8));
        mma16816(s0, fq, fk[0], fk[2]);
        mma16816(s1, fq, fk[1], fk[3]);
    }

    const float pA0 = Pv[tig * 2],     pA1 = Pv[tig * 2 + 1];
    const float pB0 = Pv[8 + tig * 2], pB1 = Pv[8 + tig * 2 + 1];
    s0[0] = s0[0] * 0.125f - GAMMA_ * pA0;
    s0[1] = s0[1] * 0.125f - GAMMA_ * pA1;
    s0[2] = s0[2] * 0.125f - GAMMA_ * pA0;
    s0[3] = s0[3] * 0.125f - GAMMA_ * pA1;
    s1[0] = s1[0] * 0.125f - GAMMA_ * pB0;
    s1[1] = s1[1] * 0.125f - GAMMA_ * pB1;
    s1[2] = s1[2] * 0.125f - GAMMA_ * pB0;
    s1[3] = s1[3] * 0.125f - GAMMA_ * pB1;

    float mA = fmaxf(fmaxf(s0[0], s0[1]), fmaxf(s1[0], s1[1]));
    float mB = fmaxf(fmaxf(s0[2], s0[3]), fmaxf(s1[2], s1[3]));
    mA = fmaxf(mA, __shfl_xor_sync(0xFFFFFFFFu, mA, 1));
    mA = fmaxf(mA, __shfl_xor_sync(0xFFFFFFFFu, mA, 2));
    mB = fmaxf(mB, __shfl_xor_sync(0xFFFFFFFFu, mB, 1));
    mB = fmaxf(mB, __shfl_xor_sync(0xFFFFFFFFu, mB, 2));
    s0[0] = expf(s0[0] - mA); s0[1] = expf(s0[1] - mA);
    s1[0] = expf(s1[0] - mA); s1[1] = expf(s1[1] - mA);
    s0[2] = expf(s0[2] - mB); s0[3] = expf(s0[3] - mB);
    s1[2] = expf(s1[2] - mB); s1[3] = expf(s1[3] - mB);
    float sumA = s0[0] + s0[1] + s1[0] + s1[1];
    float sumB = s0[2] + s0[3] + s1[2] + s1[3];
    sumA += __shfl_xor_sync(0xFFFFFFFFu, sumA, 1);
    sumA += __shfl_xor_sync(0xFFFFFFFFu, sumA, 2);
    sumB += __shfl_xor_sync(0xFFFFFFFFu, sumB, 1);
    sumB += __shfl_xor_sync(0xFFFFFFFFu, sumB, 2);
    const float invA = 1.f / sumA, invB = 1.f / sumB;

    uint32_t fa[4];
    fa[0] = pack_h2(s0[0] * invA, s0[1] * invA);
    fa[1] = pack_h2(s0[2] * invB, s0[3] * invB);
    fa[2] = pack_h2(s1[0] * invA, s1[1] * invA);
    fa[3] = pack_h2(s1[2] * invB, s1[3] * invB);

    const size_t r0 = ((size_t)(gid * NSEQ_ + n)) * D_;
    const size_t r1 = ((size_t)((gid + 8) * NSEQ_ + n)) * D_;
    #pragma unroll
    for (int eb = 0; eb < 4; eb++) {
        uint32_t fv[4];
        LDSM4T(fv, smem_cast(Vs + lrow * ATT_STRIDE + hc + eb * 16 + lchunk * 8));
        float o0[4] = {0.f, 0.f, 0.f, 0.f}, o1[4] = {0.f, 0.f, 0.f, 0.f};
        mma16816(o0, fa, fv[0], fv[1]);
        mma16816(o1, fa, fv[2], fv[3]);
        const int e0 = hc + eb * 16 + tig * 2;
        const int e1 = e0 + 8;
        *reinterpret_cast<__half2*>(g_AOf + r0 + e0) = __floats2half2_rn(o0[0], o0[1]);
        *reinterpret_cast<__half2*>(g_AOf + r1 + e0) = __floats2half2_rn(o0[2], o0[3]);
        *reinterpret_cast<__half2*>(g_AOf + r0 + e1) = __floats2half2_rn(o1[0], o1[1]);
        *reinterpret_cast<__half2*>(g_AOf + r1 + e1) = __floats2half2_rn(o1[2], o1[3]);
    }
}

// ---------------------------------------------------------------------------
extern "C" void kernel_launch(void* const* d_in, const int* in_sizes, int n_in,
                              void* d_out, int out_size)
{
    const float* h_opt = (const float*)d_in[0];
    const float* h_sar = (const float*)d_in[1];
    const float* Wq  = (const float*)d_in[2];  const float* bq  = (const float*)d_in[3];
    const float* Wk  = (const float*)d_in[4];  const float* bk  = (const float*)d_in[5];
    const float* Wv  = (const float*)d_in[6];  const float* bv  = (const float*)d_in[7];
    const float* Wo  = (const float*)d_in[8];  const float* bo  = (const float*)d_in[9];
    const float* Wp1 = (const float*)d_in[10]; const float* bp1 = (const float*)d_in[11];
    const float* Wp2 = (const float*)d_in[12]; const float* bp2 = (const float*)d_in[13];
    float* out = (float*)d_out;

    void *pQ, *pK, *pV, *pAO, *pAS, *pAOf, *pWh;
    cudaGetSymbolAddress(&pQ,  g_Qh);
    cudaGetSymbolAddress(&pK,  g_Kh);
    cudaGetSymbolAddress(&pV,  g_Vh);
    cudaGetSymbolAddress(&pAO, g_AOpt);
    cudaGetSymbolAddress(&pAS, g_ASar);
    cudaGetSymbolAddress(&pAOf, g_AOf);
    cudaGetSymbolAddress(&pWh, g_Wth);

    __half* Wth = (__half*)pWh;

    constexpr int SM_PIPE = 4 * (128 + 128) * 64;   // 65536
    constexpr int SM_SCAT = 128 * 132 * 4;          // 67584
    cudaFuncSetAttribute(gemm_qkv, cudaFuncAttributeMaxDynamicSharedMemorySize, SM_PIPE);
    cudaFuncSetAttribute(gemm_mlp, cudaFuncAttributeMaxDynamicSharedMemorySize, SM_PIPE);
    cudaFuncSetAttribute(gemm_out, cudaFuncAttributeMaxDynamicSharedMemorySize, SM_SCAT);
    cudaFuncSetAttribute(attn_kernel, cudaFuncAttributeMaxDynamicSharedMemorySize, ATT_SMEM);

    static cudaStream_t s1 = nullptr;
    static cudaEvent_t evRoot = nullptr, evG = nullptr, evW = nullptr,
                       evM = nullptr, evWo = nullptr, evA = nullptr, evO = nullptr;
    if (s1 == nullptr) {
        cudaStreamCreateWithFlags(&s1, cudaStreamNonBlocking);
        cudaEventCreateWithFlags(&evRoot, cudaEventDisableTiming);
        cudaEventCreateWithFlags(&evG,    cudaEventDisableTiming);
        cudaEventCreateWithFlags(&evW,    cudaEventDisableTiming);
        cudaEventCreateWithFlags(&evM,    cudaEventDisableTiming);
        cudaEventCreateWithFlags(&evWo,   cudaEventDisableTiming);
        cudaEventCreateWithFlags(&evA,    cudaEventDisableTiming);
        cudaEventCreateWithFlags(&evO,    cudaEventDisableTiming);
    }

    dim3 blk(256);
    cudaStream_t s0 = 0;

    cudaEventRecord(evRoot, s0);
    cudaStreamWaitEvent(s1, evRoot, 0);

    // launch 0: merged gather (s0)
    gsplit_kernel<<<dim3(16, 18, 128), blk, 0, s0>>>(h_opt, h_sar,
        (__half*)pAO, (__half*)pAS);
    cudaEventRecord(evG, s0);

    // launches 1-4: QKV + P1 weight transposes (s1, concurrent with gather)
    wsplit1_kernel<<<dim3(16, 16), blk, 0, s1>>>(Wq, 512, Wth + WOFF_Q);
    wsplit1_kernel<<<dim3(16, 16), blk, 0, s1>>>(Wk, 512, Wth + WOFF_K);
    wsplit1_kernel<<<dim3(16, 16), blk, 0, s1>>>(Wv, 512, Wth + WOFF_V);
    cudaEventRecord(evW, s1);
    wsplit1_kernel<<<dim3(4, 16), blk, 0, s1>>>(Wp1, 128, Wth + WOFF_P1);

    // launch 5: uber QKV GEMM (s0) — ncu -s 5 -c 1 profiles THIS
    cudaStreamWaitEvent(s0, evW, 0);
    gemm_qkv<<<dim3(4, 288, 3), blk, SM_PIPE, s0>>>((__half*)pAO, (__half*)pAS, Wth,
        bq, bk, bv, (__half*)pQ, (__half*)pK, (__half*)pV);

    // launch 6: Wo transpose (s0, after qkv issue; overlaps qkv tail)
    wsplit1_kernel<<<dim3(16, 16), blk, 0, s0>>>(Wo, 512, Wth + WOFF_O);
    cudaEventRecord(evWo, s0);

    // launch 7: MLP GEMM (s1, concurrent with QKV)
    cudaStreamWaitEvent(s1, evG, 0);
    gemm_mlp<<<dim3(1, 288), blk, SM_PIPE, s1>>>((__half*)pAS, Wth + WOFF_P1,
        bp1, Wp2, bp2);
    cudaEventRecord(evM, s1);

    // launches 8-9: attention halves (s0; needs QKV s0-ordered + PV)
    cudaStreamWaitEvent(s0, evM, 0);
    attn_kernel<<<1152, 256, ATT_SMEM, s0>>>(0);
    cudaEventRecord(evA, s0);
    attn_kernel<<<1152, 256, ATT_SMEM, s0>>>(1152);

    // launch 10: O-GEMM half A on s1 (overlaps attn half B on s0)
    cudaStreamWaitEvent(s1, evA, 0);
    cudaStreamWaitEvent(s1, evWo, 0);
    gemm_out<<<dim3(4, 144), blk, SM_SCAT, s1>>>((__half*)pAOf, Wth + WOFF_O, bo, out, 0);
    cudaEventRecord(evO, s1);

    // launch 11: O-GEMM half B on s0 (after attn half B, Wo s0-ordered)
    gemm_out<<<dim3(4, 144), blk, SM_SCAT, s0>>>((__half*)pAOf, Wth + WOFF_O, bo, out, 9);

    // join s1 back into s0
    cudaStreamWaitEvent(s0, evO, 0);
}

// round 14
// speedup vs baseline: 1.1965x; 1.1946x over previous
#include <cuda_runtime.h>
#include <cuda_fp16.h>
#include <math.h>
#include <stdint.h>

// ---------------- problem constants ----------------
#define B_     4
#define T_     16
#define D_     512
#define S_     576
#define NSEQ_  2304            // B_*S_
#define M_     36864           // T_*NSEQ_
#define NH_    8
#define HD_    64
#define DQ_    128
#define GAMMA_ 0.1f

// ---------------- scratch ----------------
__device__ __half g_Qh [(size_t)M_*D_];
__device__ __half g_Kh [(size_t)M_*D_];
__device__ __half g_Vh [(size_t)M_*D_];
__device__ float  g_PV [M_];

__device__ __half g_AOpt[(size_t)M_*D_];
__device__ __half g_ASar[(size_t)M_*D_];
__device__ __half g_AOf [(size_t)M_*D_];
// transposed weights, n-major [n][k], k=512, single fp16 term
#define WOFF_Q  0
#define WOFF_K  (512*512)
#define WOFF_V  (2*512*512)
#define WOFF_O  (3*512*512)
#define WOFF_P1 (4*512*512)
__device__ __half g_Wth[4*512*512 + 128*512];

// ---------------- helpers ----------------
__device__ __forceinline__ uint32_t smem_cast(const void* p) {
    uint32_t a;
    asm("{ .reg .u64 t; cvta.to.shared.u64 t, %1; cvt.u32.u64 %0, t; }" : "=r"(a) : "l"(p));
    return a;
}

#define CP16(d, s) \
    asm volatile("cp.async.cg.shared.global [%0], [%1], 16;" :: "r"(d), "l"(s) : "memory")
#define CP_COMMIT()  asm volatile("cp.async.commit_group;" ::: "memory")
#define CP_WAIT1()   asm volatile("cp.async.wait_group 1;"  ::: "memory")
#define CP_WAITALL() asm volatile("cp.async.wait_all;"      ::: "memory")

#define LDSM4(r, a) \
    asm volatile("ldmatrix.sync.aligned.m8n8.x4.shared.b16 {%0,%1,%2,%3}, [%4];" \
        : "=r"((r)[0]), "=r"((r)[1]), "=r"((r)[2]), "=r"((r)[3]) : "r"(a))
#define LDSM4T(r, a) \
    asm volatile("ldmatrix.sync.aligned.m8n8.x4.trans.shared.b16 {%0,%1,%2,%3}, [%4];" \
        : "=r"((r)[0]), "=r"((r)[1]), "=r"((r)[2]), "=r"((r)[3]) : "r"(a))

__device__ __forceinline__ void mma16816(float c[4], const uint32_t a[4],
                                         uint32_t b0, uint32_t b1) {
    asm volatile(
        "mma.sync.aligned.m16n8k16.row.col.f32.f16.f16.f32 "
        "{%0,%1,%2,%3}, {%4,%5,%6,%7}, {%8,%9}, {%0,%1,%2,%3};"
        : "+f"(c[0]), "+f"(c[1]), "+f"(c[2]), "+f"(c[3])
        : "r"(a[0]), "r"(a[1]), "r"(a[2]), "r"(a[3]), "r"(b0), "r"(b1));
}

__device__ __forceinline__ uint32_t pack_h2(float a, float b) {
    __half2 t = __floats2half2_rn(a, b);
    return *reinterpret_cast<uint32_t*>(&t);
}

// ===========================================================================
// Prepass 1: weight transpose, single fp16 term. W[k][n] f32 -> [n][k] fp16.
// ===========================================================================
__global__ __launch_bounds__(256) void wsplit1_kernel(
    const float* __restrict__ W, int ncols, __half* __restrict__ oh)
{
    __shared__ float tile[32][33];
    const int n0 = blockIdx.x * 32, k0 = blockIdx.y * 32;
    const int tx = threadIdx.x & 31, ty = threadIdx.x >> 5;
    #pragma unroll
    for (int p = 0; p < 4; p++)
        tile[ty + p * 8][tx] = W[(size_t)(k0 + ty + p * 8) * ncols + n0 + tx];
    __syncthreads();
    #pragma unroll
    for (int p = 0; p < 4; p++) {
        const int row = ty + p * 8;
        oh[(size_t)(n0 + row) * 512 + k0 + tx] = __float2half_rn(tile[tx][row]);
    }
}

// ===========================================================================
// Prepass 2: merged gather, both inputs. Tile = 64 k x 32 sp.
// z < 64: opt; z >= 64: sar. 128B coalesced half2 row writes.
// ===========================================================================
__global__ __launch_bounds__(256) void gsplit_kernel(
    const float* __restrict__ Aopt, const float* __restrict__ Asar,
    __half* __restrict__ Oopt, __half* __restrict__ Osar)
{
    __shared__ float tile[64][33];   // [k][sp]
    const int k0 = blockIdx.x * 64, sp0 = blockIdx.y * 32;
    int z = blockIdx.z;
    const float* Ain = (z < 64) ? Aopt : Asar;
    __half* oh = (z < 64) ? Oopt : Osar;
    z &= 63;
    const int b = z >> 4, t = z & 15;
    const int tx = threadIdx.x & 31, ty = threadIdx.x >> 5;
    const size_t base = ((size_t)(b * T_ + t) * D_) * S_;
    #pragma unroll
    for (int p = 0; p < 8; p++)
        tile[ty + p * 8][tx] = Ain[base + (size_t)(k0 + ty + p * 8) * S_ + sp0 + tx];
    __syncthreads();
    const int mb = t * NSEQ_ + b * S_ + sp0;
    #pragma unroll
    for (int it = 0; it < 4; it++) {
        const int idx = threadIdx.x + it * 256;   // 0..1023
        const int sp = idx >> 5, kp = idx & 31;
        __half2 h = __floats2half2_rn(tile[2 * kp][sp], tile[2 * kp + 1][sp]);
        *reinterpret_cast<__half2*>(oh + (size_t)(mb + sp) * 512 + k0 + 2 * kp) = h;
    }
}

// ===========================================================================
// GEMM core. BM=BN=128, BK=64 (128B rows, conflict-free c^(row&7) swizzle),
// 3-stage cp.async (32KB/stage), 2 CTAs/SM, ldmatrix.
// ===========================================================================
__device__ __forceinline__ void gemm_mainloop(
    const __half* __restrict__ A, const __half* __restrict__ Bh,
    int m0, int j0, uint32_t sbase, int tid, float acc[4][4][4])
{
    constexpr int BM = 128, BN = 128;
    constexpr int OFF_BH = BM * 128;          // 16384
    constexpr int STG = (BM + BN) * 128;      // 32768

    const int lane = tid & 31;
    const int wid = tid >> 5;
    const int wm = wid >> 2, wn = wid & 3;

    #pragma unroll
    for (int i = 0; i < 4; i++)
        #pragma unroll
        for (int j = 0; j < 4; j++)
            #pragma unroll
            for (int q = 0; q < 4; q++) acc[i][j][q] = 0.f;

    auto issue = [&](int kt) {
        const int s = kt % 3;
        const int k0 = kt * 64;
        const uint32_t d0 = sbase + s * STG;
        #pragma unroll
        for (int it = 0; it < 8; it++) {
            const int idx = tid + it * 256;       // 0..2047
            const int row = idx >> 3, c = idx & 7;
            if (row < BM) {
                const uint32_t d = d0 + ((row * 8 + (c ^ (row & 7))) << 4);
                CP16(d, A + (size_t)(m0 + row) * 512 + k0 + c * 8);
            } else {
                const int br = row - BM;
                const uint32_t d = d0 + OFF_BH + ((br * 8 + (c ^ (br & 7))) << 4);
                CP16(d, Bh + (size_t)(j0 + br) * 512 + k0 + c * 8);
            }
        }
    };

    issue(0); CP_COMMIT();
    issue(1); CP_COMMIT();

    #pragma unroll 1
    for (int kt = 0; kt < 8; kt++) {
        CP_WAIT1();
        __syncthreads();
        if (kt + 2 < 8) issue(kt + 2);
        CP_COMMIT();

        const int s = kt % 3;
        const uint32_t sa   = sbase + s * STG;
        const uint32_t sb_h = sa + OFF_BH;

        #pragma unroll
        for (int ks = 0; ks < 4; ks++) {
            uint32_t fa[4][4], fbh[2][4];
            #pragma unroll
            for (int i = 0; i < 4; i++) {
                const int row = wm * 64 + i * 16 + (lane & 15);
                const int c = ks * 2 + (lane >> 4);
                const uint32_t off = (uint32_t)((row * 8 + (c ^ (row & 7))) << 4);
                LDSM4(fa[i], sa + off);
            }
            #pragma unroll
            for (int jb = 0; jb < 2; jb++) {
                const int row = wn * 32 + jb * 16 + (lane & 15);
                const int c = ks * 2 + (lane >> 4);
                const uint32_t off = (uint32_t)((row * 8 + (c ^ (row & 7))) << 4);
                LDSM4(fbh[jb], sb_h + off);
            }
            #pragma unroll
            for (int i = 0; i < 4; i++)
                #pragma unroll
                for (int j = 0; j < 4; j++) {
                    const int jb = j >> 1, sel = j & 1;
                    mma16816(acc[i][j], fa[i], fbh[jb][sel], fbh[jb][sel + 2]);
                }
        }
    }
}

// ===========================================================================
// Uber QKV GEMM: blockIdx.z in {0,1,2} selects {Q, K, V}. Half output.
// ===========================================================================
__global__ __launch_bounds__(256, 2) void gemm_qkv(
    const __half* __restrict__ Aopt, const __half* __restrict__ Asar,
    const __half* __restrict__ Wth,
    const float* __restrict__ bq, const float* __restrict__ bk,
    const float* __restrict__ bv,
    __half* __restrict__ Qh, __half* __restrict__ Kh, __half* __restrict__ Vh)
{
    extern __shared__ char smraw[];
    const uint32_t sbase = smem_cast(smraw);
    const int tid = threadIdx.x;
    const int m0 = blockIdx.y * 128, j0 = blockIdx.x * 128;
    const int z = blockIdx.z;

    const __half* A  = (z == 0) ? Aopt : Asar;
    const __half* Bh = Wth + ((z == 0) ? WOFF_Q : (z == 1) ? WOFF_K : WOFF_V);
    const float* bias = (z == 0) ? bq : (z == 1) ? bk : bv;
    __half* Ch = (z == 0) ? Qh : (z == 1) ? Kh : Vh;

    float acc[4][4][4];
    gemm_mainloop(A, Bh, m0, j0, sbase, tid, acc);

    const int lane = tid & 31, wid = tid >> 5;
    const int wm = wid >> 2, wn = wid & 3;
    const int gid = lane >> 2, tig = lane & 3;
    #pragma unroll
    for (int i = 0; i < 4; i++) {
        const int row0 = m0 + wm * 64 + i * 16 + gid;
        #pragma unroll
        for (int j = 0; j < 4; j++) {
            const int col = j0 + wn * 32 + j * 8 + tig * 2;
            const float b0 = __ldg(bias + col), b1 = __ldg(bias + col + 1);
            *reinterpret_cast<__half2*>(Ch + (size_t)row0 * D_ + col)
                = __floats2half2_rn(acc[i][j][0] + b0, acc[i][j][1] + b1);
            *reinterpret_cast<__half2*>(Ch + (size_t)(row0 + 8) * D_ + col)
                = __floats2half2_rn(acc[i][j][2] + b0, acc[i][j][3] + b1);
        }
    }
}

// ===========================================================================
// MLP GEMM: gelu -> dot(Wp2) -> reduce -> sigmoid -> g_PV. grid (1, 288).
// ===========================================================================
__global__ __launch_bounds__(256, 2) void gemm_mlp(
    const __half* __restrict__ A, const __half* __restrict__ Bh,
    const float* __restrict__ bias,
    const float* __restrict__ Wp2, const float* __restrict__ bp2)
{
    extern __shared__ char smraw[];
    const uint32_t sbase = smem_cast(smraw);
    const int tid = threadIdx.x;
    const int m0 = blockIdx.y * 128;

    float acc[4][4][4];
    gemm_mainloop(A, Bh, m0, 0, sbase, tid, acc);

    const int lane = tid & 31, wid = tid >> 5;
    const int wm = wid >> 2, wn = wid & 3;
    const int gid = lane >> 2, tig = lane & 3;

    CP_WAITALL();
    __syncthreads();
    float* red = reinterpret_cast<float*>(smraw);   // [4 wn][128 rows]
    #pragma unroll
    for (int i = 0; i < 4; i++) {
        const int r0 = wm * 64 + i * 16 + gid;
        float p0 = 0.f, p1 = 0.f;
        #pragma unroll
        for (int j = 0; j < 4; j++) {
            const int col = wn * 32 + j * 8 + tig * 2;
            const float b0 = __ldg(bias + col), b1 = __ldg(bias + col + 1);
            const float w0 = __ldg(Wp2 + col),  w1 = __ldg(Wp2 + col + 1);
            float v0 = acc[i][j][0] + b0; v0 *= normcdff(v0);
            float v1 = acc[i][j][1] + b1; v1 *= normcdff(v1);
            float v2 = acc[i][j][2] + b0; v2 *= normcdff(v2);
            float v3 = acc[i][j][3] + b1; v3 *= normcdff(v3);
            p0 += v0 * w0 + v1 * w1;
            p1 += v2 * w0 + v3 * w1;
        }
        p0 += __shfl_xor_sync(0xFFFFFFFFu, p0, 1);
        p0 += __shfl_xor_sync(0xFFFFFFFFu, p0, 2);
        p1 += __shfl_xor_sync(0xFFFFFFFFu, p1, 1);
        p1 += __shfl_xor_sync(0xFFFFFFFFu, p1, 2);
        if (tig == 0) {
            red[wn * 128 + r0]     = p0;
            red[wn * 128 + r0 + 8] = p1;
        }
    }
    __syncthreads();
    if (tid < 128) {
        float x = red[tid] + red[128 + tid] + red[256 + tid] + red[384 + tid] + bp2[0];
        g_PV[m0 + tid] = 1.f / (1.f + expf(-x));
    }
}

// ===========================================================================
// Output GEMM with fused scatter into 5D (B,T,D,24,24) float out.
// ===========================================================================
__global__ __launch_bounds__(256, 2) void gemm_out(
    const __half* __restrict__ A, const __half* __restrict__ Bh,
    const float* __restrict__ bias, float* __restrict__ Cf)
{
    extern __shared__ char smraw[];
    const uint32_t sbase = smem_cast(smraw);
    const int tid = threadIdx.x;
    const int m0 = blockIdx.y * 128, j0 = blockIdx.x * 128;

    float acc[4][4][4];
    gemm_mainloop(A, Bh, m0, j0, sbase, tid, acc);

    const int lane = tid & 31, wid = tid >> 5;
    const int wm = wid >> 2, wn = wid & 3;
    const int gid = lane >> 2, tig = lane & 3;

    CP_WAITALL();
    __syncthreads();
    float* Csm = reinterpret_cast<float*>(smraw);   // [128][132]
    #pragma unroll
    for (int i = 0; i < 4; i++) {
        const int row0 = wm * 64 + i * 16 + gid;
        #pragma unroll
        for (int j = 0; j < 4; j++) {
            const int col = wn * 32 + j * 8 + tig * 2;
            const float b0 = __ldg(bias + j0 + col), b1 = __ldg(bias + j0 + col + 1);
            Csm[(col)     * 132 + row0]     = acc[i][j][0] + b0;
            Csm[(col + 1) * 132 + row0]     = acc[i][j][1] + b1;
            Csm[(col)     * 132 + row0 + 8] = acc[i][j][2] + b0;
            Csm[(col + 1) * 132 + row0 + 8] = acc[i][j][3] + b1;
        }
    }
    __syncthreads();
    const int t  = m0 / NSEQ_;
    const int n0 = m0 % NSEQ_;
    #pragma unroll 4
    for (int idx = tid; idx < 128 * 128; idx += 256) {
        const int j = idx >> 7, mr = idx & 127;
        const int n = n0 + mr;
        const int b = n / S_, sp = n % S_;
        Cf[((size_t)((b * T_ + t) * D_) + j0 + j) * S_ + sp] = Csm[j * 132 + mr];
    }
}

// ===========================================================================
// Attention (mma.sync): one block per n (256 thr, warp = head).
// ===========================================================================
#define ATT_STRIDE 520
#define ATT_SMEM   (3 * 16 * ATT_STRIDE * 2 + 64)

__global__ __launch_bounds__(256) void attn_kernel()
{
    extern __shared__ char araw[];
    __half* Qs = reinterpret_cast<__half*>(araw);
    __half* Ks = Qs + 16 * ATT_STRIDE;
    __half* Vs = Ks + 16 * ATT_STRIDE;
    float*  Pv = reinterpret_cast<float*>(Vs + 16 * ATT_STRIDE);

    const int n = blockIdx.x;
    const int tid = threadIdx.x;
    const int lane = tid & 31, w = tid >> 5;
    const int gid = lane >> 2, tig = lane & 3;
    const int lrow = lane & 15, lchunk = lane >> 4;

    #pragma unroll
    for (int i = 0; i < 4; i++) {
        int idx = tid + i * 256;
        int t = idx >> 6, c = (idx & 63) * 8;
        size_t src = ((size_t)(t * NSEQ_ + n)) * D_ + c;
        *reinterpret_cast<float4*>(Qs + t * ATT_STRIDE + c) =
            *reinterpret_cast<const float4*>(g_Qh + src);
        *reinterpret_cast<float4*>(Ks + t * ATT_STRIDE + c) =
            *reinterpret_cast<const float4*>(g_Kh + src);
        *reinterpret_cast<float4*>(Vs + t * ATT_STRIDE + c) =
            *reinterpret_cast<const float4*>(g_Vh + src);
    }
    if (tid < 16) Pv[tid] = g_PV[tid * NSEQ_ + n];
    __syncthreads();

    const int hc = w * HD_;

    float s0[4] = {0.f, 0.f, 0.f, 0.f}, s1[4] = {0.f, 0.f, 0.f, 0.f};
    #pragma unroll
    for (int kk = 0; kk < 4; kk++) {
        uint32_t fq[4], fk[4];
        LDSM4(fq, smem_cast(Qs + lrow * ATT_STRIDE + hc + kk * 16 + lchunk * 8));
        LDSM4(fk, smem_cast(Ks + lrow * ATT_STRIDE + hc + kk * 16 + lchunk * 8));
        mma16816(s0, fq, fk[0], fk[2]);
        mma16816(s1, fq, fk[1], fk[3]);
    }

    const float pA0 = Pv[tig * 2],     pA1 = Pv[tig * 2 + 1];
    const float pB0 = Pv[8 + tig * 2], pB1 = Pv[8 + tig * 2 + 1];
    s0[0] = s0[0] * 0.125f - GAMMA_ * pA0;
    s0[1] = s0[1] * 0.125f - GAMMA_ * pA1;
    s0[2] = s0[2] * 0.125f - GAMMA_ * pA0;
    s0[3] = s0[3] * 0.125f - GAMMA_ * pA1;
    s1[0] = s1[0] * 0.125f - GAMMA_ * pB0;
    s1[1] = s1[1] * 0.125f - GAMMA_ * pB1;
    s1[2] = s1[2] * 0.125f - GAMMA_ * pB0;
    s1[3] = s1[3] * 0.125f - GAMMA_ * pB1;

    float mA = fmaxf(fmaxf(s0[0], s0[1]), fmaxf(s1[0], s1[1]));
    float mB = fmaxf(fmaxf(s0[2], s0[3]), fmaxf(s1[2], s1[3]));
    mA = fmaxf(mA, __shfl_xor_sync(0xFFFFFFFFu, mA, 1));
    mA = fmaxf(mA, __shfl_xor_sync(0xFFFFFFFFu, mA, 2));
    mB = fmaxf(mB, __shfl_xor_sync(0xFFFFFFFFu, mB, 1));
    mB = fmaxf(mB, __shfl_xor_sync(0xFFFFFFFFu, mB, 2));
    s0[0] = expf(s0[0] - mA); s0[1] = expf(s0[1] - mA);
    s1[0] = expf(s1[0] - mA); s1[1] = expf(s1[1] - mA);
    s0[2] = expf(s0[2] - mB); s0[3] = expf(s0[3] - mB);
    s1[2] = expf(s1[2] - mB); s1[3] = expf(s1[3] - mB);
    float sumA = s0[0] + s0[1] + s1[0] + s1[1];
    float sumB = s0[2] + s0[3] + s1[2] + s1[3];
    sumA += __shfl_xor_sync(0xFFFFFFFFu, sumA, 1);
    sumA += __shfl_xor_sync(0xFFFFFFFFu, sumA, 2);
    sumB += __shfl_xor_sync(0xFFFFFFFFu, sumB, 1);
    sumB += __shfl_xor_sync(0xFFFFFFFFu, sumB, 2);
    const float invA = 1.f / sumA, invB = 1.f / sumB;

    uint32_t fa[4];
    fa[0] = pack_h2(s0[0] * invA, s0[1] * invA);
    fa[1] = pack_h2(s0[2] * invB, s0[3] * invB);
    fa[2] = pack_h2(s1[0] * invA, s1[1] * invA);
    fa[3] = pack_h2(s1[2] * invB, s1[3] * invB);

    const size_t r0 = ((size_t)(gid * NSEQ_ + n)) * D_;
    const size_t r1 = ((size_t)((gid + 8) * NSEQ_ + n)) * D_;
    #pragma unroll
    for (int eb = 0; eb < 4; eb++) {
        uint32_t fv[4];
        LDSM4T(fv, smem_cast(Vs + lrow * ATT_STRIDE + hc + eb * 16 + lchunk * 8));
        float o0[4] = {0.f, 0.f, 0.f, 0.f}, o1[4] = {0.f, 0.f, 0.f, 0.f};
        mma16816(o0, fa, fv[0], fv[1]);
        mma16816(o1, fa, fv[2], fv[3]);
        const int e0 = hc + eb * 16 + tig * 2;
        const int e1 = e0 + 8;
        *reinterpret_cast<__half2*>(g_AOf + r0 + e0) = __floats2half2_rn(o0[0], o0[1]);
        *reinterpret_cast<__half2*>(g_AOf + r1 + e0) = __floats2half2_rn(o0[2], o0[3]);
        *reinterpret_cast<__half2*>(g_AOf + r0 + e1) = __floats2half2_rn(o1[0], o1[1]);
        *reinterpret_cast<__half2*>(g_AOf + r1 + e1) = __floats2half2_rn(o1[2], o1[3]);
    }
}

// ---------------------------------------------------------------------------
extern "C" void kernel_launch(void* const* d_in, const int* in_sizes, int n_in,
                              void* d_out, int out_size)
{
    const float* h_opt = (const float*)d_in[0];
    const float* h_sar = (const float*)d_in[1];
    const float* Wq  = (const float*)d_in[2];  const float* bq  = (const float*)d_in[3];
    const float* Wk  = (const float*)d_in[4];  const float* bk  = (const float*)d_in[5];
    const float* Wv  = (const float*)d_in[6];  const float* bv  = (const float*)d_in[7];
    const float* Wo  = (const float*)d_in[8];  const float* bo  = (const float*)d_in[9];
    const float* Wp1 = (const float*)d_in[10]; const float* bp1 = (const float*)d_in[11];
    const float* Wp2 = (const float*)d_in[12]; const float* bp2 = (const float*)d_in[13];
    float* out = (float*)d_out;

    void *pQ, *pK, *pV, *pAO, *pAS, *pAOf, *pWh;
    cudaGetSymbolAddress(&pQ,  g_Qh);
    cudaGetSymbolAddress(&pK,  g_Kh);
    cudaGetSymbolAddress(&pV,  g_Vh);
    cudaGetSymbolAddress(&pAO, g_AOpt);
    cudaGetSymbolAddress(&pAS, g_ASar);
    cudaGetSymbolAddress(&pAOf, g_AOf);
    cudaGetSymbolAddress(&pWh, g_Wth);

    __half* Wth = (__half*)pWh;

    constexpr int SM_PIPE = 3 * (128 + 128) * 128;  // 98304
    cudaFuncSetAttribute(gemm_qkv, cudaFuncAttributeMaxDynamicSharedMemorySize, SM_PIPE);
    cudaFuncSetAttribute(gemm_mlp, cudaFuncAttributeMaxDynamicSharedMemorySize, SM_PIPE);
    cudaFuncSetAttribute(gemm_out, cudaFuncAttributeMaxDynamicSharedMemorySize, SM_PIPE);
    cudaFuncSetAttribute(attn_kernel, cudaFuncAttributeMaxDynamicSharedMemorySize, ATT_SMEM);

    static cudaStream_t s1 = nullptr;
    static cudaEvent_t evRoot = nullptr, evG = nullptr, evW = nullptr, evM = nullptr;
    if (s1 == nullptr) {
        cudaStreamCreateWithFlags(&s1, cudaStreamNonBlocking);
        cudaEventCreateWithFlags(&evRoot, cudaEventDisableTiming);
        cudaEventCreateWithFlags(&evG,    cudaEventDisableTiming);
        cudaEventCreateWithFlags(&evW,    cudaEventDisableTiming);
        cudaEventCreateWithFlags(&evM,    cudaEventDisableTiming);
    }

    dim3 blk(256);
    cudaStream_t s0 = 0;

    cudaEventRecord(evRoot, s0);
    cudaStreamWaitEvent(s1, evRoot, 0);

    // S0: merged gather (opt + sar), 64k x 32sp tiles
    gsplit_kernel<<<dim3(8, 18, 128), blk, 0, s0>>>(h_opt, h_sar,
        (__half*)pAO, (__half*)pAS);
    cudaEventRecord(evG, s0);

    // S1: all weight transposes (concurrent with gather), then MLP GEMM
    wsplit1_kernel<<<dim3(16, 16), blk, 0, s1>>>(Wq, 512, Wth + WOFF_Q);
    wsplit1_kernel<<<dim3(16, 16), blk, 0, s1>>>(Wk, 512, Wth + WOFF_K);
    wsplit1_kernel<<<dim3(16, 16), blk, 0, s1>>>(Wv, 512, Wth + WOFF_V);
    cudaEventRecord(evW, s1);
    wsplit1_kernel<<<dim3(4, 16), blk, 0, s1>>>(Wp1, 128, Wth + WOFF_P1);
    wsplit1_kernel<<<dim3(16, 16), blk, 0, s1>>>(Wo, 512, Wth + WOFF_O);
    cudaStreamWaitEvent(s1, evG, 0);
    gemm_mlp<<<dim3(1, 288), blk, SM_PIPE, s1>>>((__half*)pAS, Wth + WOFF_P1,
        bp1, Wp2, bp2);
    cudaEventRecord(evM, s1);

    // S0: uber QKV GEMM (waits on QKV weights)
    cudaStreamWaitEvent(s0, evW, 0);
    gemm_qkv<<<dim3(4, 288, 3), blk, SM_PIPE, s0>>>((__half*)pAO, (__half*)pAS, Wth,
        bq, bk, bv, (__half*)pQ, (__half*)pK, (__half*)pV);

    // join: attention needs QKV (s0) and PV (s1); evM also orders Wo
    cudaStreamWaitEvent(s0, evM, 0);
    attn_kernel<<<NSEQ_, 256, ATT_SMEM, s0>>>();

    // output projection + fused scatter
    gemm_out<<<dim3(4, 288), blk, SM_PIPE, s0>>>((__half*)pAOf, Wth + WOFF_O, bo, out);
}

// round 15
// speedup vs baseline: 1.2180x; 1.0180x over previous
#include <cuda_runtime.h>
#include <cuda_fp16.h>
#include <math.h>
#include <stdint.h>

// ---------------- problem constants ----------------
#define B_     4
#define T_     16
#define D_     512
#define S_     576
#define NSEQ_  2304            // B_*S_
#define M_     36864           // T_*NSEQ_
#define NH_    8
#define HD_    64
#define DQ_    128
#define GAMMA_ 0.1f

// ---------------- scratch ----------------
__device__ __half g_Qh [(size_t)M_*D_];
__device__ __half g_Kh [(size_t)M_*D_];
__device__ __half g_Vh [(size_t)M_*D_];
__device__ float  g_PV [M_];

__device__ __half g_AOpt[(size_t)M_*D_];
__device__ __half g_ASar[(size_t)M_*D_];
__device__ __half g_AOf [(size_t)M_*D_];
// transposed weights, n-major [n][k], k=512, single fp16 term
#define WOFF_Q  0
#define WOFF_K  (512*512)
#define WOFF_V  (2*512*512)
#define WOFF_O  (3*512*512)
#define WOFF_P1 (4*512*512)
__device__ __half g_Wth[4*512*512 + 128*512];

// ---------------- helpers ----------------
__device__ __forceinline__ uint32_t smem_cast(const void* p) {
    uint32_t a;
    asm("{ .reg .u64 t; cvta.to.shared.u64 t, %1; cvt.u32.u64 %0, t; }" : "=r"(a) : "l"(p));
    return a;
}

#define CP16(d, s) \
    asm volatile("cp.async.cg.shared.global [%0], [%1], 16;" :: "r"(d), "l"(s) : "memory")
#define CP_COMMIT()  asm volatile("cp.async.commit_group;" ::: "memory")
#define CP_WAIT1()   asm volatile("cp.async.wait_group 1;"  ::: "memory")
#define CP_WAITALL() asm volatile("cp.async.wait_all;"      ::: "memory")

#define LDSM4(r, a) \
    asm volatile("ldmatrix.sync.aligned.m8n8.x4.shared.b16 {%0,%1,%2,%3}, [%4];" \
        : "=r"((r)[0]), "=r"((r)[1]), "=r"((r)[2]), "=r"((r)[3]) : "r"(a))
#define LDSM4T(r, a) \
    asm volatile("ldmatrix.sync.aligned.m8n8.x4.trans.shared.b16 {%0,%1,%2,%3}, [%4];" \
        : "=r"((r)[0]), "=r"((r)[1]), "=r"((r)[2]), "=r"((r)[3]) : "r"(a))

__device__ __forceinline__ void mma16816(float c[4], const uint32_t a[4],
                                         uint32_t b0, uint32_t b1) {
    asm volatile(
        "mma.sync.aligned.m16n8k16.row.col.f32.f16.f16.f32 "
        "{%0,%1,%2,%3}, {%4,%5,%6,%7}, {%8,%9}, {%0,%1,%2,%3};"
        : "+f"(c[0]), "+f"(c[1]), "+f"(c[2]), "+f"(c[3])
        : "r"(a[0]), "r"(a[1]), "r"(a[2]), "r"(a[3]), "r"(b0), "r"(b1));
}

__device__ __forceinline__ uint32_t pack_h2(float a, float b) {
    __half2 t = __floats2half2_rn(a, b);
    return *reinterpret_cast<uint32_t*>(&t);
}

// ===========================================================================
// Uber weight transpose: z selects {Wq, Wk, Wv, Wo, Wp1}. f32 [k][n] -> fp16 [n][k].
// ===========================================================================
__global__ __launch_bounds__(256) void wsplit_all(
    const float* __restrict__ Wq, const float* __restrict__ Wk,
    const float* __restrict__ Wv, const float* __restrict__ Wo,
    const float* __restrict__ Wp1, __half* __restrict__ Wth)
{
    const int z = blockIdx.z;
    if (z == 4 && blockIdx.x >= 4) return;
    const float* W = (z == 0) ? Wq : (z == 1) ? Wk : (z == 2) ? Wv : (z == 3) ? Wo : Wp1;
    const int ncols = (z == 4) ? 128 : 512;
    __half* oh = Wth + ((z == 0) ? WOFF_Q : (z == 1) ? WOFF_K : (z == 2) ? WOFF_V
                       : (z == 3) ? WOFF_O : WOFF_P1);

    __shared__ float tile[32][33];
    const int n0 = blockIdx.x * 32, k0 = blockIdx.y * 32;
    const int tx = threadIdx.x & 31, ty = threadIdx.x >> 5;
    #pragma unroll
    for (int p = 0; p < 4; p++)
        tile[ty + p * 8][tx] = W[(size_t)(k0 + ty + p * 8) * ncols + n0 + tx];
    __syncthreads();
    #pragma unroll
    for (int p = 0; p < 4; p++) {
        const int row = ty + p * 8;
        oh[(size_t)(n0 + row) * 512 + k0 + tx] = __float2half_rn(tile[tx][row]);
    }
}

// ===========================================================================
// Gather: (B,T,D,24,24) f32 -> [m][k] fp16. Tile = 64 k x 64 sp, float2 loads.
// grid (8, 9, 64).
// ===========================================================================
__global__ __launch_bounds__(256) void gather_kernel(
    const float* __restrict__ Ain, __half* __restrict__ oh)
{
    __shared__ float tile[64][65];   // [k][sp]
    const int k0 = blockIdx.x * 64, sp0 = blockIdx.y * 64;
    const int z = blockIdx.z;
    const int b = z >> 4, t = z & 15;
    const int tx = threadIdx.x & 31, ty = threadIdx.x >> 5;   // tx: sp-pair, ty: row
    const size_t base = ((size_t)(b * T_ + t) * D_) * S_;
    #pragma unroll
    for (int p = 0; p < 8; p++) {
        const int row = ty + p * 8;
        float2 v = *reinterpret_cast<const float2*>(
            Ain + base + (size_t)(k0 + row) * S_ + sp0 + tx * 2);
        tile[row][tx * 2]     = v.x;
        tile[row][tx * 2 + 1] = v.y;
    }
    __syncthreads();
    const int mb = t * NSEQ_ + b * S_ + sp0;
    #pragma unroll
    for (int it = 0; it < 8; it++) {
        const int idx = threadIdx.x + it * 256;   // 0..2047
        const int sp = idx >> 5, kp = idx & 31;
        __half2 h = __floats2half2_rn(tile[2 * kp][sp], tile[2 * kp + 1][sp]);
        *reinterpret_cast<__half2*>(oh + (size_t)(mb + sp) * 512 + k0 + 2 * kp) = h;
    }
}

// ===========================================================================
// GEMM core. BM=BN=128, BK=64 (128B rows, conflict-free c^(row&7) swizzle),
// 3-stage cp.async (32KB/stage), 2 CTAs/SM, ldmatrix.
// ===========================================================================
__device__ __forceinline__ void gemm_mainloop(
    const __half* __restrict__ A, const __half* __restrict__ Bh,
    int m0, int j0, uint32_t sbase, int tid, float acc[4][4][4])
{
    constexpr int BM = 128, BN = 128;
    constexpr int OFF_BH = BM * 128;          // 16384
    constexpr int STG = (BM + BN) * 128;      // 32768

    const int lane = tid & 31;
    const int wid = tid >> 5;
    const int wm = wid >> 2, wn = wid & 3;

    #pragma unroll
    for (int i = 0; i < 4; i++)
        #pragma unroll
        for (int j = 0; j < 4; j++)
            #pragma unroll
            for (int q = 0; q < 4; q++) acc[i][j][q] = 0.f;

    auto issue = [&](int kt) {
        const int s = kt % 3;
        const int k0 = kt * 64;
        const uint32_t d0 = sbase + s * STG;
        #pragma unroll
        for (int it = 0; it < 8; it++) {
            const int idx = tid + it * 256;       // 0..2047
            const int row = idx >> 3, c = idx & 7;
            if (row < BM) {
                const uint32_t d = d0 + ((row * 8 + (c ^ (row & 7))) << 4);
                CP16(d, A + (size_t)(m0 + row) * 512 + k0 + c * 8);
            } else {
                const int br = row - BM;
                const uint32_t d = d0 + OFF_BH + ((br * 8 + (c ^ (br & 7))) << 4);
                CP16(d, Bh + (size_t)(j0 + br) * 512 + k0 + c * 8);
            }
        }
    };

    issue(0); CP_COMMIT();
    issue(1); CP_COMMIT();

    #pragma unroll 1
    for (int kt = 0; kt < 8; kt++) {
        CP_WAIT1();
        __syncthreads();
        if (kt + 2 < 8) issue(kt + 2);
        CP_COMMIT();

        const int s = kt % 3;
        const uint32_t sa   = sbase + s * STG;
        const uint32_t sb_h = sa + OFF_BH;

        #pragma unroll
        for (int ks = 0; ks < 4; ks++) {
            uint32_t fa[4][4], fbh[2][4];
            #pragma unroll
            for (int i = 0; i < 4; i++) {
                const int row = wm * 64 + i * 16 + (lane & 15);
                const int c = ks * 2 + (lane >> 4);
                const uint32_t off = (uint32_t)((row * 8 + (c ^ (row & 7))) << 4);
                LDSM4(fa[i], sa + off);
            }
            #pragma unroll
            for (int jb = 0; jb < 2; jb++) {
                const int row = wn * 32 + jb * 16 + (lane & 15);
                const int c = ks * 2 + (lane >> 4);
                const uint32_t off = (uint32_t)((row * 8 + (c ^ (row & 7))) << 4);
                LDSM4(fbh[jb], sb_h + off);
            }
            #pragma unroll
            for (int i = 0; i < 4; i++)
                #pragma unroll
                for (int j = 0; j < 4; j++) {
                    const int jb = j >> 1, sel = j & 1;
                    mma16816(acc[i][j], fa[i], fbh[jb][sel], fbh[jb][sel + 2]);
                }
        }
    }
}

// half-output epilogue (bias add)
__device__ __forceinline__ void epi_half(
    float acc[4][4][4], const float* __restrict__ bias, __half* __restrict__ Ch,
    int m0, int j0, int tid)
{
    const int lane = tid & 31, wid = tid >> 5;
    const int wm = wid >> 2, wn = wid & 3;
    const int gid = lane >> 2, tig = lane & 3;
    #pragma unroll
    for (int i = 0; i < 4; i++) {
        const int row0 = m0 + wm * 64 + i * 16 + gid;
        #pragma unroll
        for (int j = 0; j < 4; j++) {
            const int col = j0 + wn * 32 + j * 8 + tig * 2;
            const float b0 = __ldg(bias + col), b1 = __ldg(bias + col + 1);
            *reinterpret_cast<__half2*>(Ch + (size_t)row0 * D_ + col)
                = __floats2half2_rn(acc[i][j][0] + b0, acc[i][j][1] + b1);
            *reinterpret_cast<__half2*>(Ch + (size_t)(row0 + 8) * D_ + col)
                = __floats2half2_rn(acc[i][j][2] + b0, acc[i][j][3] + b1);
        }
    }
}

// Q projection: grid (4, 288)
__global__ __launch_bounds__(256, 2) void gemm_q(
    const __half* __restrict__ A, const __half* __restrict__ Bh,
    const float* __restrict__ bias, __half* __restrict__ Ch)
{
    extern __shared__ char smraw[];
    float acc[4][4][4];
    gemm_mainloop(A, Bh, blockIdx.y * 128, blockIdx.x * 128,
                  smem_cast(smraw), threadIdx.x, acc);
    epi_half(acc, bias, Ch, blockIdx.y * 128, blockIdx.x * 128, threadIdx.x);
}

// K/V projections: grid (4, 288, 2)
__global__ __launch_bounds__(256, 2) void gemm_kv(
    const __half* __restrict__ A, const __half* __restrict__ Wth,
    const float* __restrict__ bk, const float* __restrict__ bv,
    __half* __restrict__ Kh, __half* __restrict__ Vh)
{
    extern __shared__ char smraw[];
    const int z = blockIdx.z;
    const __half* Bh = Wth + ((z == 0) ? WOFF_K : WOFF_V);
    const float* bias = (z == 0) ? bk : bv;
    __half* Ch = (z == 0) ? Kh : Vh;
    float acc[4][4][4];
    gemm_mainloop(A, Bh, blockIdx.y * 128, blockIdx.x * 128,
                  smem_cast(smraw), threadIdx.x, acc);
    epi_half(acc, bias, Ch, blockIdx.y * 128, blockIdx.x * 128, threadIdx.x);
}

// ===========================================================================
// MLP GEMM: gelu -> dot(Wp2) -> reduce -> sigmoid -> g_PV. grid (1, 288).
// ===========================================================================
__global__ __launch_bounds__(256, 2) void gemm_mlp(
    const __half* __restrict__ A, const __half* __restrict__ Bh,
    const float* __restrict__ bias,
    const float* __restrict__ Wp2, const float* __restrict__ bp2)
{
    extern __shared__ char smraw[];
    const uint32_t sbase = smem_cast(smraw);
    const int tid = threadIdx.x;
    const int m0 = blockIdx.y * 128;

    float acc[4][4][4];
    gemm_mainloop(A, Bh, m0, 0, sbase, tid, acc);

    const int lane = tid & 31, wid = tid >> 5;
    const int wm = wid >> 2, wn = wid & 3;
    const int gid = lane >> 2, tig = lane & 3;

    CP_WAITALL();
    __syncthreads();
    float* red = reinterpret_cast<float*>(smraw);   // [4 wn][128 rows]
    #pragma unroll
    for (int i = 0; i < 4; i++) {
        const int r0 = wm * 64 + i * 16 + gid;
        float p0 = 0.f, p1 = 0.f;
        #pragma unroll
        for (int j = 0; j < 4; j++) {
            const int col = wn * 32 + j * 8 + tig * 2;
            const float b0 = __ldg(bias + col), b1 = __ldg(bias + col + 1);
            const float w0 = __ldg(Wp2 + col),  w1 = __ldg(Wp2 + col + 1);
            float v0 = acc[i][j][0] + b0; v0 *= normcdff(v0);
            float v1 = acc[i][j][1] + b1; v1 *= normcdff(v1);
            float v2 = acc[i][j][2] + b0; v2 *= normcdff(v2);
            float v3 = acc[i][j][3] + b1; v3 *= normcdff(v3);
            p0 += v0 * w0 + v1 * w1;
            p1 += v2 * w0 + v3 * w1;
        }
        p0 += __shfl_xor_sync(0xFFFFFFFFu, p0, 1);
        p0 += __shfl_xor_sync(0xFFFFFFFFu, p0, 2);
        p1 += __shfl_xor_sync(0xFFFFFFFFu, p1, 1);
        p1 += __shfl_xor_sync(0xFFFFFFFFu, p1, 2);
        if (tig == 0) {
            red[wn * 128 + r0]     = p0;
            red[wn * 128 + r0 + 8] = p1;
        }
    }
    __syncthreads();
    if (tid < 128) {
        float x = red[tid] + red[128 + tid] + red[256 + tid] + red[384 + tid] + bp2[0];
        g_PV[m0 + tid] = 1.f / (1.f + expf(-x));
    }
}

// ===========================================================================
// Output GEMM with fused scatter into 5D (B,T,D,24,24) float out.
// ===========================================================================
__global__ __launch_bounds__(256, 2) void gemm_out(
    const __half* __restrict__ A, const __half* __restrict__ Bh,
    const float* __restrict__ bias, float* __restrict__ Cf)
{
    extern __shared__ char smraw[];
    const uint32_t sbase = smem_cast(smraw);
    const int tid = threadIdx.x;
    const int m0 = blockIdx.y * 128, j0 = blockIdx.x * 128;

    float acc[4][4][4];
    gemm_mainloop(A, Bh, m0, j0, sbase, tid, acc);

    const int lane = tid & 31, wid = tid >> 5;
    const int wm = wid >> 2, wn = wid & 3;
    const int gid = lane >> 2, tig = lane & 3;

    CP_WAITALL();
    __syncthreads();
    float* Csm = reinterpret_cast<float*>(smraw);   // [128][132]
    #pragma unroll
    for (int i = 0; i < 4; i++) {
        const int row0 = wm * 64 + i * 16 + gid;
        #pragma unroll
        for (int j = 0; j < 4; j++) {
            const int col = wn * 32 + j * 8 + tig * 2;
            const float b0 = __ldg(bias + j0 + col), b1 = __ldg(bias + j0 + col + 1);
            Csm[(col)     * 132 + row0]     = acc[i][j][0] + b0;
            Csm[(col + 1) * 132 + row0]     = acc[i][j][1] + b1;
            Csm[(col)     * 132 + row0 + 8] = acc[i][j][2] + b0;
            Csm[(col + 1) * 132 + row0 + 8] = acc[i][j][3] + b1;
        }
    }
    __syncthreads();
    const int t  = m0 / NSEQ_;
    const int n0 = m0 % NSEQ_;
    #pragma unroll 4
    for (int idx = tid; idx < 128 * 128; idx += 256) {
        const int j = idx >> 7, mr = idx & 127;
        const int n = n0 + mr;
        const int b = n / S_, sp = n % S_;
        Cf[((size_t)((b * T_ + t) * D_) + j0 + j) * S_ + sp] = Csm[j * 132 + mr];
    }
}

// ===========================================================================
// Attention (mma.sync): one block per n (256 thr, warp = head).
// ===========================================================================
#define ATT_STRIDE 520
#define ATT_SMEM   (3 * 16 * ATT_STRIDE * 2 + 64)

__global__ __launch_bounds__(256) void attn_kernel()
{
    extern __shared__ char araw[];
    __half* Qs = reinterpret_cast<__half*>(araw);
    __half* Ks = Qs + 16 * ATT_STRIDE;
    __half* Vs = Ks + 16 * ATT_STRIDE;
    float*  Pv = reinterpret_cast<float*>(Vs + 16 * ATT_STRIDE);

    const int n = blockIdx.x;
    const int tid = threadIdx.x;
    const int lane = tid & 31, w = tid >> 5;
    const int gid = lane >> 2, tig = lane & 3;
    const int lrow = lane & 15, lchunk = lane >> 4;

    #pragma unroll
    for (int i = 0; i < 4; i++) {
        int idx = tid + i * 256;
        int t = idx >> 6, c = (idx & 63) * 8;
        size_t src = ((size_t)(t * NSEQ_ + n)) * D_ + c;
        *reinterpret_cast<float4*>(Qs + t * ATT_STRIDE + c) =
            *reinterpret_cast<const float4*>(g_Qh + src);
        *reinterpret_cast<float4*>(Ks + t * ATT_STRIDE + c) =
            *reinterpret_cast<const float4*>(g_Kh + src);
        *reinterpret_cast<float4*>(Vs + t * ATT_STRIDE + c) =
            *reinterpret_cast<const float4*>(g_Vh + src);
    }
    if (tid < 16) Pv[tid] = g_PV[tid * NSEQ_ + n];
    __syncthreads();

    const int hc = w * HD_;

    float s0[4] = {0.f, 0.f, 0.f, 0.f}, s1[4] = {0.f, 0.f, 0.f, 0.f};
    #pragma unroll
    for (int kk = 0; kk < 4; kk++) {
        uint32_t fq[4], fk[4];
        LDSM4(fq, smem_cast(Qs + lrow * ATT_STRIDE + hc + kk * 16 + lchunk * 8));
        LDSM4(fk, smem_cast(Ks + lrow * ATT_STRIDE + hc + kk * 16 + lchunk * 8));
        mma16816(s0, fq, fk[0], fk[2]);
        mma16816(s1, fq, fk[1], fk[3]);
    }

    const float pA0 = Pv[tig * 2],     pA1 = Pv[tig * 2 + 1];
    const float pB0 = Pv[8 + tig * 2], pB1 = Pv[8 + tig * 2 + 1];
    s0[0] = s0[0] * 0.125f - GAMMA_ * pA0;
    s0[1] = s0[1] * 0.125f - GAMMA_ * pA1;
    s0[2] = s0[2] * 0.125f - GAMMA_ * pA0;
    s0[3] = s0[3] * 0.125f - GAMMA_ * pA1;
    s1[0] = s1[0] * 0.125f - GAMMA_ * pB0;
    s1[1] = s1[1] * 0.125f - GAMMA_ * pB1;
    s1[2] = s1[2] * 0.125f - GAMMA_ * pB0;
    s1[3] = s1[3] * 0.125f - GAMMA_ * pB1;

    float mA = fmaxf(fmaxf(s0[0], s0[1]), fmaxf(s1[0], s1[1]));
    float mB = fmaxf(fmaxf(s0[2], s0[3]), fmaxf(s1[2], s1[3]));
    mA = fmaxf(mA, __shfl_xor_sync(0xFFFFFFFFu, mA, 1));
    mA = fmaxf(mA, __shfl_xor_sync(0xFFFFFFFFu, mA, 2));
    mB = fmaxf(mB, __shfl_xor_sync(0xFFFFFFFFu, mB, 1));
    mB = fmaxf(mB, __shfl_xor_sync(0xFFFFFFFFu, mB, 2));
    s0[0] = expf(s0[0] - mA); s0[1] = expf(s0[1] - mA);
    s1[0] = expf(s1[0] - mA); s1[1] = expf(s1[1] - mA);
    s0[2] = expf(s0[2] - mB); s0[3] = expf(s0[3] - mB);
    s1[2] = expf(s1[2] - mB); s1[3] = expf(s1[3] - mB);
    float sumA = s0[0] + s0[1] + s1[0] + s1[1];
    float sumB = s0[2] + s0[3] + s1[2] + s1[3];
    sumA += __shfl_xor_sync(0xFFFFFFFFu, sumA, 1);
    sumA += __shfl_xor_sync(0xFFFFFFFFu, sumA, 2);
    sumB += __shfl_xor_sync(0xFFFFFFFFu, sumB, 1);
    sumB += __shfl_xor_sync(0xFFFFFFFFu, sumB, 2);
    const float invA = 1.f / sumA, invB = 1.f / sumB;

    uint32_t fa[4];
    fa[0] = pack_h2(s0[0] * invA, s0[1] * invA);
    fa[1] = pack_h2(s0[2] * invB, s0[3] * invB);
    fa[2] = pack_h2(s1[0] * invA, s1[1] * invA);
    fa[3] = pack_h2(s1[2] * invB, s1[3] * invB);

    const size_t r0 = ((size_t)(gid * NSEQ_ + n)) * D_;
    const size_t r1 = ((size_t)((gid + 8) * NSEQ_ + n)) * D_;
    #pragma unroll
    for (int eb = 0; eb < 4; eb++) {
        uint32_t fv[4];
        LDSM4T(fv, smem_cast(Vs + lrow * ATT_STRIDE + hc + eb * 16 + lchunk * 8));
        float o0[4] = {0.f, 0.f, 0.f, 0.f}, o1[4] = {0.f, 0.f, 0.f, 0.f};
        mma16816(o0, fa, fv[0], fv[1]);
        mma16816(o1, fa, fv[2], fv[3]);
        const int e0 = hc + eb * 16 + tig * 2;
        const int e1 = e0 + 8;
        *reinterpret_cast<__half2*>(g_AOf + r0 + e0) = __floats2half2_rn(o0[0], o0[1]);
        *reinterpret_cast<__half2*>(g_AOf + r1 + e0) = __floats2half2_rn(o0[2], o0[3]);
        *reinterpret_cast<__half2*>(g_AOf + r0 + e1) = __floats2half2_rn(o1[0], o1[1]);
        *reinterpret_cast<__half2*>(g_AOf + r1 + e1) = __floats2half2_rn(o1[2], o1[3]);
    }
}

// ---------------------------------------------------------------------------
extern "C" void kernel_launch(void* const* d_in, const int* in_sizes, int n_in,
                              void* d_out, int out_size)
{
    const float* h_opt = (const float*)d_in[0];
    const float* h_sar = (const float*)d_in[1];
    const float* Wq  = (const float*)d_in[2];  const float* bq  = (const float*)d_in[3];
    const float* Wk  = (const float*)d_in[4];  const float* bk  = (const float*)d_in[5];
    const float* Wv  = (const float*)d_in[6];  const float* bv  = (const float*)d_in[7];
    const float* Wo  = (const float*)d_in[8];  const float* bo  = (const float*)d_in[9];
    const float* Wp1 = (const float*)d_in[10]; const float* bp1 = (const float*)d_in[11];
    const float* Wp2 = (const float*)d_in[12]; const float* bp2 = (const float*)d_in[13];
    float* out = (float*)d_out;

    void *pQ, *pK, *pV, *pAO, *pAS, *pAOf, *pWh;
    cudaGetSymbolAddress(&pQ,  g_Qh);
    cudaGetSymbolAddress(&pK,  g_Kh);
    cudaGetSymbolAddress(&pV,  g_Vh);
    cudaGetSymbolAddress(&pAO, g_AOpt);
    cudaGetSymbolAddress(&pAS, g_ASar);
    cudaGetSymbolAddress(&pAOf, g_AOf);
    cudaGetSymbolAddress(&pWh, g_Wth);

    __half* Wth = (__half*)pWh;

    constexpr int SM_PIPE = 3 * (128 + 128) * 128;  // 98304
    cudaFuncSetAttribute(gemm_q,   cudaFuncAttributeMaxDynamicSharedMemorySize, SM_PIPE);
    cudaFuncSetAttribute(gemm_kv,  cudaFuncAttributeMaxDynamicSharedMemorySize, SM_PIPE);
    cudaFuncSetAttribute(gemm_mlp, cudaFuncAttributeMaxDynamicSharedMemorySize, SM_PIPE);
    cudaFuncSetAttribute(gemm_out, cudaFuncAttributeMaxDynamicSharedMemorySize, SM_PIPE);
    cudaFuncSetAttribute(attn_kernel, cudaFuncAttributeMaxDynamicSharedMemorySize, ATT_SMEM);

    static cudaStream_t s1 = nullptr;
    static cudaEvent_t evRoot = nullptr, evW = nullptr, evSar = nullptr, evM = nullptr;
    if (s1 == nullptr) {
        cudaStreamCreateWithFlags(&s1, cudaStreamNonBlocking);
        cudaEventCreateWithFlags(&evRoot, cudaEventDisableTiming);
        cudaEventCreateWithFlags(&evW,    cudaEventDisableTiming);
        cudaEventCreateWithFlags(&evSar,  cudaEventDisableTiming);
        cudaEventCreateWithFlags(&evM,    cudaEventDisableTiming);
    }

    dim3 blk(256);
    cudaStream_t s0 = 0;

    cudaEventRecord(evRoot, s0);
    cudaStreamWaitEvent(s1, evRoot, 0);

    // launch 1 (s0): opt gather
    gather_kernel<<<dim3(8, 9, 64), blk, 0, s0>>>(h_opt, (__half*)pAO);

    // launch 2 (s1): all weight transposes
    wsplit_all<<<dim3(16, 16, 5), blk, 0, s1>>>(Wq, Wk, Wv, Wo, Wp1, Wth);
    cudaEventRecord(evW, s1);

    // launch 3 (s1): sar gather
    gather_kernel<<<dim3(8, 9, 64), blk, 0, s1>>>(h_sar, (__half*)pAS);
    cudaEventRecord(evSar, s1);

    // launch 4 (s1): MLP GEMM (sar + Wp1 ready on s1)
    gemm_mlp<<<dim3(1, 288), blk, SM_PIPE, s1>>>((__half*)pAS, Wth + WOFF_P1,
        bp1, Wp2, bp2);
    cudaEventRecord(evM, s1);

    // launch 5 (s0): Q GEMM — overlaps sar gather + MLP on s1
    cudaStreamWaitEvent(s0, evW, 0);
    gemm_q<<<dim3(4, 288), blk, SM_PIPE, s0>>>((__half*)pAO, Wth + WOFF_Q,
        bq, (__half*)pQ);

    // launch 6 (s0): K/V GEMMs (profiled by ncu -s 5 -c 1)
    cudaStreamWaitEvent(s0, evSar, 0);
    gemm_kv<<<dim3(4, 288, 2), blk, SM_PIPE, s0>>>((__half*)pAS, Wth,
        bk, bv, (__half*)pK, (__half*)pV);

    // launch 7 (s0): attention (needs QKV on s0, PV via evM)
    cudaStreamWaitEvent(s0, evM, 0);
    attn_kernel<<<NSEQ_, 256, ATT_SMEM, s0>>>();

    // launch 8 (s0): output projection + fused scatter
    gemm_out<<<dim3(4, 288), blk, SM_PIPE, s0>>>((__half*)pAOf, Wth + WOFF_O, bo, out);
}

// round 16
// speedup vs baseline: 1.2642x; 1.0379x over previous
#include <cuda_runtime.h>
#include <cuda_fp16.h>
#include <math.h>
#include <stdint.h>

// ---------------- problem constants ----------------
#define B_     4
#define T_     16
#define D_     512
#define S_     576
#define NSEQ_  2304            // B_*S_
#define M_     36864           // T_*NSEQ_
#define NH_    8
#define HD_    64
#define DQ_    128
#define GAMMA_ 0.1f

// ---------------- scratch ----------------
__device__ __half g_Qh [(size_t)M_*D_];
__device__ __half g_Kh [(size_t)M_*D_];
__device__ __half g_Vh [(size_t)M_*D_];
__device__ float  g_PV [M_];

__device__ __half g_AOpt[(size_t)M_*D_];
__device__ __half g_ASar[(size_t)M_*D_];
__device__ __half g_AOf [(size_t)M_*D_];
// transposed weights, n-major [n][k], k=512, single fp16 term
#define WOFF_Q  0
#define WOFF_K  (512*512)
#define WOFF_V  (2*512*512)
#define WOFF_O  (3*512*512)
#define WOFF_P1 (4*512*512)
__device__ __half g_Wth[4*512*512 + 128*512];

// ---------------- helpers ----------------
__device__ __forceinline__ uint32_t smem_cast(const void* p) {
    uint32_t a;
    asm("{ .reg .u64 t; cvta.to.shared.u64 t, %1; cvt.u32.u64 %0, t; }" : "=r"(a) : "l"(p));
    return a;
}

#define CP16(d, s) \
    asm volatile("cp.async.cg.shared.global [%0], [%1], 16;" :: "r"(d), "l"(s) : "memory")
#define CP_COMMIT()  asm volatile("cp.async.commit_group;" ::: "memory")
#define CP_WAIT1()   asm volatile("cp.async.wait_group 1;"  ::: "memory")
#define CP_WAITALL() asm volatile("cp.async.wait_all;"      ::: "memory")

#define LDSM4(r, a) \
    asm volatile("ldmatrix.sync.aligned.m8n8.x4.shared.b16 {%0,%1,%2,%3}, [%4];" \
        : "=r"((r)[0]), "=r"((r)[1]), "=r"((r)[2]), "=r"((r)[3]) : "r"(a))
#define LDSM4T(r, a) \
    asm volatile("ldmatrix.sync.aligned.m8n8.x4.trans.shared.b16 {%0,%1,%2,%3}, [%4];" \
        : "=r"((r)[0]), "=r"((r)[1]), "=r"((r)[2]), "=r"((r)[3]) : "r"(a))

__device__ __forceinline__ void mma16816(float c[4], const uint32_t a[4],
                                         uint32_t b0, uint32_t b1) {
    asm volatile(
        "mma.sync.aligned.m16n8k16.row.col.f32.f16.f16.f32 "
        "{%0,%1,%2,%3}, {%4,%5,%6,%7}, {%8,%9}, {%0,%1,%2,%3};"
        : "+f"(c[0]), "+f"(c[1]), "+f"(c[2]), "+f"(c[3])
        : "r"(a[0]), "r"(a[1]), "r"(a[2]), "r"(a[3]), "r"(b0), "r"(b1));
}

__device__ __forceinline__ uint32_t pack_h2(float a, float b) {
    __half2 t = __floats2half2_rn(a, b);
    return *reinterpret_cast<uint32_t*>(&t);
}

// ===========================================================================
// Uber weight transpose: z selects {Wq, Wk, Wv, Wo, Wp1}. f32 [k][n] -> fp16 [n][k].
// ===========================================================================
__global__ __launch_bounds__(256) void wsplit_all(
    const float* __restrict__ Wq, const float* __restrict__ Wk,
    const float* __restrict__ Wv, const float* __restrict__ Wo,
    const float* __restrict__ Wp1, __half* __restrict__ Wth)
{
    const int z = blockIdx.z;
    if (z == 4 && blockIdx.x >= 4) return;
    const float* W = (z == 0) ? Wq : (z == 1) ? Wk : (z == 2) ? Wv : (z == 3) ? Wo : Wp1;
    const int ncols = (z == 4) ? 128 : 512;
    __half* oh = Wth + ((z == 0) ? WOFF_Q : (z == 1) ? WOFF_K : (z == 2) ? WOFF_V
                       : (z == 3) ? WOFF_O : WOFF_P1);

    __shared__ float tile[32][33];
    const int n0 = blockIdx.x * 32, k0 = blockIdx.y * 32;
    const int tx = threadIdx.x & 31, ty = threadIdx.x >> 5;
    #pragma unroll
    for (int p = 0; p < 4; p++)
        tile[ty + p * 8][tx] = W[(size_t)(k0 + ty + p * 8) * ncols + n0 + tx];
    __syncthreads();
    #pragma unroll
    for (int p = 0; p < 4; p++) {
        const int row = ty + p * 8;
        oh[(size_t)(n0 + row) * 512 + k0 + tx] = __float2half_rn(tile[tx][row]);
    }
}

// ===========================================================================
// Gather: (B,T,D,24,24) f32 -> [m][k] fp16. Tile = 64 k x 64 sp, float2 loads.
// grid (8, 9, 64).
// ===========================================================================
__global__ __launch_bounds__(256) void gather_kernel(
    const float* __restrict__ Ain, __half* __restrict__ oh)
{
    __shared__ float tile[64][65];   // [k][sp]
    const int k0 = blockIdx.x * 64, sp0 = blockIdx.y * 64;
    const int z = blockIdx.z;
    const int b = z >> 4, t = z & 15;
    const int tx = threadIdx.x & 31, ty = threadIdx.x >> 5;
    const size_t base = ((size_t)(b * T_ + t) * D_) * S_;
    #pragma unroll
    for (int p = 0; p < 8; p++) {
        const int row = ty + p * 8;
        float2 v = *reinterpret_cast<const float2*>(
            Ain + base + (size_t)(k0 + row) * S_ + sp0 + tx * 2);
        tile[row][tx * 2]     = v.x;
        tile[row][tx * 2 + 1] = v.y;
    }
    __syncthreads();
    const int mb = t * NSEQ_ + b * S_ + sp0;
    #pragma unroll
    for (int it = 0; it < 8; it++) {
        const int idx = threadIdx.x + it * 256;   // 0..2047
        const int sp = idx >> 5, kp = idx & 31;
        __half2 h = __floats2half2_rn(tile[2 * kp][sp], tile[2 * kp + 1][sp]);
        *reinterpret_cast<__half2*>(oh + (size_t)(mb + sp) * 512 + k0 + 2 * kp) = h;
    }
}

// ===========================================================================
// GEMM core. BM=BN=128, BK=64 (128B rows, conflict-free c^(row&7) swizzle),
// 3-stage cp.async (32KB/stage), 2 CTAs/SM, ldmatrix.
// All addresses precomputed per-thread; kt loop fully unrolled.
// ===========================================================================
#define G_OFF_BH 16384
#define G_STG    32768

__device__ __forceinline__ void gemm_mainloop(
    const __half* __restrict__ A, const __half* __restrict__ Bh,
    int m0, int j0, uint32_t sbase, int tid, float acc[4][4][4])
{
    const int lane = tid & 31;
    const int wid = tid >> 5;
    const int wm = wid >> 2, wn = wid & 3;

    #pragma unroll
    for (int i = 0; i < 4; i++)
        #pragma unroll
        for (int j = 0; j < 4; j++)
            #pragma unroll
            for (int q = 0; q < 4; q++) acc[i][j][q] = 0.f;

    // ---- producer constants: c = tid&7, rows r0 + it*32 ----
    const int pc = tid & 7, pr0 = tid >> 3;
    const __half* aptr = A  + (size_t)(m0 + pr0) * 512 + pc * 8;
    const __half* bptr = Bh + (size_t)(j0 + pr0) * 512 + pc * 8;
    const uint32_t dbase = (uint32_t)((pr0 * 8 + (pc ^ (pr0 & 7))) << 4);

    auto issue = [&](int kt) {
        const uint32_t d0 = sbase + (uint32_t)((kt % 3) * G_STG) + dbase;
        const int koff = kt * 64;
        #pragma unroll
        for (int it = 0; it < 4; it++) {
            CP16(d0 + it * 4096,            aptr + (size_t)it * 32 * 512 + koff);
            CP16(d0 + G_OFF_BH + it * 4096, bptr + (size_t)it * 32 * 512 + koff);
        }
    };

    // ---- consumer constants ----
    uint32_t rowAoff[4], rowBoff[2], csoff[4];
    #pragma unroll
    for (int i = 0; i < 4; i++)
        rowAoff[i] = (uint32_t)((wm * 64 + i * 16 + (lane & 15)) << 7);
    #pragma unroll
    for (int jb = 0; jb < 2; jb++)
        rowBoff[jb] = (uint32_t)((wn * 32 + jb * 16 + (lane & 15)) << 7) + G_OFF_BH;
    #pragma unroll
    for (int ks = 0; ks < 4; ks++)
        csoff[ks] = (uint32_t)(((ks * 2 + (lane >> 4)) ^ (lane & 7)) << 4);

    issue(0); CP_COMMIT();
    issue(1); CP_COMMIT();

    #pragma unroll
    for (int kt = 0; kt < 8; kt++) {
        CP_WAIT1();
        __syncthreads();
        if (kt + 2 < 8) issue(kt + 2);
        CP_COMMIT();

        const uint32_t sa = sbase + (uint32_t)((kt % 3) * G_STG);

        #pragma unroll
        for (int ks = 0; ks < 4; ks++) {
            uint32_t fa[4][4], fbh[2][4];
            #pragma unroll
            for (int i = 0; i < 4; i++)
                LDSM4(fa[i], sa + rowAoff[i] + csoff[ks]);
            #pragma unroll
            for (int jb = 0; jb < 2; jb++)
                LDSM4(fbh[jb], sa + rowBoff[jb] + csoff[ks]);
            #pragma unroll
            for (int i = 0; i < 4; i++)
                #pragma unroll
                for (int j = 0; j < 4; j++) {
                    const int jb = j >> 1, sel = j & 1;
                    mma16816(acc[i][j], fa[i], fbh[jb][sel], fbh[jb][sel + 2]);
                }
        }
    }
}

// half-output epilogue (bias add)
__device__ __forceinline__ void epi_half(
    float acc[4][4][4], const float* __restrict__ bias, __half* __restrict__ Ch,
    int m0, int j0, int tid)
{
    const int lane = tid & 31, wid = tid >> 5;
    const int wm = wid >> 2, wn = wid & 3;
    const int gid = lane >> 2, tig = lane & 3;
    #pragma unroll
    for (int i = 0; i < 4; i++) {
        const int row0 = m0 + wm * 64 + i * 16 + gid;
        #pragma unroll
        for (int j = 0; j < 4; j++) {
            const int col = j0 + wn * 32 + j * 8 + tig * 2;
            const float b0 = __ldg(bias + col), b1 = __ldg(bias + col + 1);
            *reinterpret_cast<__half2*>(Ch + (size_t)row0 * D_ + col)
                = __floats2half2_rn(acc[i][j][0] + b0, acc[i][j][1] + b1);
            *reinterpret_cast<__half2*>(Ch + (size_t)(row0 + 8) * D_ + col)
                = __floats2half2_rn(acc[i][j][2] + b0, acc[i][j][3] + b1);
        }
    }
}

// Q projection: grid (4, 288)
__global__ __launch_bounds__(256, 2) void gemm_q(
    const __half* __restrict__ A, const __half* __restrict__ Bh,
    const float* __restrict__ bias, __half* __restrict__ Ch)
{
    extern __shared__ char smraw[];
    float acc[4][4][4];
    gemm_mainloop(A, Bh, blockIdx.y * 128, blockIdx.x * 128,
                  smem_cast(smraw), threadIdx.x, acc);
    epi_half(acc, bias, Ch, blockIdx.y * 128, blockIdx.x * 128, threadIdx.x);
}

// K/V projections: grid (4, 288, 2)
__global__ __launch_bounds__(256, 2) void gemm_kv(
    const __half* __restrict__ A, const __half* __restrict__ Wth,
    const float* __restrict__ bk, const float* __restrict__ bv,
    __half* __restrict__ Kh, __half* __restrict__ Vh)
{
    extern __shared__ char smraw[];
    const int z = blockIdx.z;
    const __half* Bh = Wth + ((z == 0) ? WOFF_K : WOFF_V);
    const float* bias = (z == 0) ? bk : bv;
    __half* Ch = (z == 0) ? Kh : Vh;
    float acc[4][4][4];
    gemm_mainloop(A, Bh, blockIdx.y * 128, blockIdx.x * 128,
                  smem_cast(smraw), threadIdx.x, acc);
    epi_half(acc, bias, Ch, blockIdx.y * 128, blockIdx.x * 128, threadIdx.x);
}

// ===========================================================================
// MLP GEMM: gelu -> dot(Wp2) -> reduce -> sigmoid -> g_PV. grid (1, 288).
// ===========================================================================
__global__ __launch_bounds__(256, 2) void gemm_mlp(
    const __half* __restrict__ A, const __half* __restrict__ Bh,
    const float* __restrict__ bias,
    const float* __restrict__ Wp2, const float* __restrict__ bp2)
{
    extern __shared__ char smraw[];
    const uint32_t sbase = smem_cast(smraw);
    const int tid = threadIdx.x;
    const int m0 = blockIdx.y * 128;

    float acc[4][4][4];
    gemm_mainloop(A, Bh, m0, 0, sbase, tid, acc);

    const int lane = tid & 31, wid = tid >> 5;
    const int wm = wid >> 2, wn = wid & 3;
    const int gid = lane >> 2, tig = lane & 3;

    CP_WAITALL();
    __syncthreads();
    float* red = reinterpret_cast<float*>(smraw);   // [4 wn][128 rows]
    #pragma unroll
    for (int i = 0; i < 4; i++) {
        const int r0 = wm * 64 + i * 16 + gid;
        float p0 = 0.f, p1 = 0.f;
        #pragma unroll
        for (int j = 0; j < 4; j++) {
            const int col = wn * 32 + j * 8 + tig * 2;
            const float b0 = __ldg(bias + col), b1 = __ldg(bias + col + 1);
            const float w0 = __ldg(Wp2 + col),  w1 = __ldg(Wp2 + col + 1);
            float v0 = acc[i][j][0] + b0; v0 *= normcdff(v0);
            float v1 = acc[i][j][1] + b1; v1 *= normcdff(v1);
            float v2 = acc[i][j][2] + b0; v2 *= normcdff(v2);
            float v3 = acc[i][j][3] + b1; v3 *= normcdff(v3);
            p0 += v0 * w0 + v1 * w1;
            p1 += v2 * w0 + v3 * w1;
        }
        p0 += __shfl_xor_sync(0xFFFFFFFFu, p0, 1);
        p0 += __shfl_xor_sync(0xFFFFFFFFu, p0, 2);
        p1 += __shfl_xor_sync(0xFFFFFFFFu, p1, 1);
        p1 += __shfl_xor_sync(0xFFFFFFFFu, p1, 2);
        if (tig == 0) {
            red[wn * 128 + r0]     = p0;
            red[wn * 128 + r0 + 8] = p1;
        }
    }
    __syncthreads();
    if (tid < 128) {
        float x = red[tid] + red[128 + tid] + red[256 + tid] + red[384 + tid] + bp2[0];
        g_PV[m0 + tid] = 1.f / (1.f + expf(-x));
    }
}

// ===========================================================================
// Output GEMM with fused scatter into 5D (B,T,D,24,24) float out.
// ===========================================================================
__global__ __launch_bounds__(256, 2) void gemm_out(
    const __half* __restrict__ A, const __half* __restrict__ Bh,
    const float* __restrict__ bias, float* __restrict__ Cf)
{
    extern __shared__ char smraw[];
    const uint32_t sbase = smem_cast(smraw);
    const int tid = threadIdx.x;
    const int m0 = blockIdx.y * 128, j0 = blockIdx.x * 128;

    float acc[4][4][4];
    gemm_mainloop(A, Bh, m0, j0, sbase, tid, acc);

    const int lane = tid & 31, wid = tid >> 5;
    const int wm = wid >> 2, wn = wid & 3;
    const int gid = lane >> 2, tig = lane & 3;

    CP_WAITALL();
    __syncthreads();
    float* Csm = reinterpret_cast<float*>(smraw);   // [128][132]
    #pragma unroll
    for (int i = 0; i < 4; i++) {
        const int row0 = wm * 64 + i * 16 + gid;
        #pragma unroll
        for (int j = 0; j < 4; j++) {
            const int col = wn * 32 + j * 8 + tig * 2;
            const float b0 = __ldg(bias + j0 + col), b1 = __ldg(bias + j0 + col + 1);
            Csm[(col)     * 132 + row0]     = acc[i][j][0] + b0;
            Csm[(col + 1) * 132 + row0]     = acc[i][j][1] + b1;
            Csm[(col)     * 132 + row0 + 8] = acc[i][j][2] + b0;
            Csm[(col + 1) * 132 + row0 + 8] = acc[i][j][3] + b1;
        }
    }
    __syncthreads();
    const int t  = m0 / NSEQ_;
    const int n0 = m0 % NSEQ_;
    #pragma unroll 4
    for (int idx = tid; idx < 128 * 128; idx += 256) {
        const int j = idx >> 7, mr = idx & 127;
        const int n = n0 + mr;
        const int b = n / S_, sp = n % S_;
        Cf[((size_t)((b * T_ + t) * D_) + j0 + j) * S_ + sp] = Csm[j * 132 + mr];
    }
}

// ===========================================================================
// Attention (mma.sync): one block per n (256 thr, warp = head).
// ===========================================================================
#define ATT_STRIDE 520
#define ATT_SMEM   (3 * 16 * ATT_STRIDE * 2 + 64)

__global__ __launch_bounds__(256) void attn_kernel()
{
    extern __shared__ char araw[];
    __half* Qs = reinterpret_cast<__half*>(araw);
    __half* Ks = Qs + 16 * ATT_STRIDE;
    __half* Vs = Ks + 16 * ATT_STRIDE;
    float*  Pv = reinterpret_cast<float*>(Vs + 16 * ATT_STRIDE);

    const int n = blockIdx.x;
    const int tid = threadIdx.x;
    const int lane = tid & 31, w = tid >> 5;
    const int gid = lane >> 2, tig = lane & 3;
    const int lrow = lane & 15, lchunk = lane >> 4;

    #pragma unroll
    for (int i = 0; i < 4; i++) {
        int idx = tid + i * 256;
        int t = idx >> 6, c = (idx & 63) * 8;
        size_t src = ((size_t)(t * NSEQ_ + n)) * D_ + c;
        *reinterpret_cast<float4*>(Qs + t * ATT_STRIDE + c) =
            *reinterpret_cast<const float4*>(g_Qh + src);
        *reinterpret_cast<float4*>(Ks + t * ATT_STRIDE + c) =
            *reinterpret_cast<const float4*>(g_Kh + src);
        *reinterpret_cast<float4*>(Vs + t * ATT_STRIDE + c) =
            *reinterpret_cast<const float4*>(g_Vh + src);
    }
    if (tid < 16) Pv[tid] = g_PV[tid * NSEQ_ + n];
    __syncthreads();

    const int hc = w * HD_;

    float s0[4] = {0.f, 0.f, 0.f, 0.f}, s1[4] = {0.f, 0.f, 0.f, 0.f};
    #pragma unroll
    for (int kk = 0; kk < 4; kk++) {
        uint32_t fq[4], fk[4];
        LDSM4(fq, smem_cast(Qs + lrow * ATT_STRIDE + hc + kk * 16 + lchunk * 8));
        LDSM4(fk, smem_cast(Ks + lrow * ATT_STRIDE + hc + kk * 16 + lchunk * 8));
        mma16816(s0, fq, fk[0], fk[2]);
        mma16816(s1, fq, fk[1], fk[3]);
    }

    const float pA0 = Pv[tig * 2],     pA1 = Pv[tig * 2 + 1];
    const float pB0 = Pv[8 + tig * 2], pB1 = Pv[8 + tig * 2 + 1];
    s0[0] = s0[0] * 0.125f - GAMMA_ * pA0;
    s0[1] = s0[1] * 0.125f - GAMMA_ * pA1;
    s0[2] = s0[2] * 0.125f - GAMMA_ * pA0;
    s0[3] = s0[3] * 0.125f - GAMMA_ * pA1;
    s1[0] = s1[0] * 0.125f - GAMMA_ * pB0;
    s1[1] = s1[1] * 0.125f - GAMMA_ * pB1;
    s1[2] = s1[2] * 0.125f - GAMMA_ * pB0;
    s1[3] = s1[3] * 0.125f - GAMMA_ * pB1;

    float mA = fmaxf(fmaxf(s0[0], s0[1]), fmaxf(s1[0], s1[1]));
    float mB = fmaxf(fmaxf(s0[2], s0[3]), fmaxf(s1[2], s1[3]));
    mA = fmaxf(mA, __shfl_xor_sync(0xFFFFFFFFu, mA, 1));
    mA = fmaxf(mA, __shfl_xor_sync(0xFFFFFFFFu, mA, 2));
    mB = fmaxf(mB, __shfl_xor_sync(0xFFFFFFFFu, mB, 1));
    mB = fmaxf(mB, __shfl_xor_sync(0xFFFFFFFFu, mB, 2));
    s0[0] = expf(s0[0] - mA); s0[1] = expf(s0[1] - mA);
    s1[0] = expf(s1[0] - mA); s1[1] = expf(s1[1] - mA);
    s0[2] = expf(s0[2] - mB); s0[3] = expf(s0[3] - mB);
    s1[2] = expf(s1[2] - mB); s1[3] = expf(s1[3] - mB);
    float sumA = s0[0] + s0[1] + s1[0] + s1[1];
    float sumB = s0[2] + s0[3] + s1[2] + s1[3];
    sumA += __shfl_xor_sync(0xFFFFFFFFu, sumA, 1);
    sumA += __shfl_xor_sync(0xFFFFFFFFu, sumA, 2);
    sumB += __shfl_xor_sync(0xFFFFFFFFu, sumB, 1);
    sumB += __shfl_xor_sync(0xFFFFFFFFu, sumB, 2);
    const float invA = 1.f / sumA, invB = 1.f / sumB;

    uint32_t fa[4];
    fa[0] = pack_h2(s0[0] * invA, s0[1] * invA);
    fa[1] = pack_h2(s0[2] * invB, s0[3] * invB);
    fa[2] = pack_h2(s1[0] * invA, s1[1] * invA);
    fa[3] = pack_h2(s1[2] * invB, s1[3] * invB);

    const size_t r0 = ((size_t)(gid * NSEQ_ + n)) * D_;
    const size_t r1 = ((size_t)((gid + 8) * NSEQ_ + n)) * D_;
    #pragma unroll
    for (int eb = 0; eb < 4; eb++) {
        uint32_t fv[4];
        LDSM4T(fv, smem_cast(Vs + lrow * ATT_STRIDE + hc + eb * 16 + lchunk * 8));
        float o0[4] = {0.f, 0.f, 0.f, 0.f}, o1[4] = {0.f, 0.f, 0.f, 0.f};
        mma16816(o0, fa, fv[0], fv[1]);
        mma16816(o1, fa, fv[2], fv[3]);
        const int e0 = hc + eb * 16 + tig * 2;
        const int e1 = e0 + 8;
        *reinterpret_cast<__half2*>(g_AOf + r0 + e0) = __floats2half2_rn(o0[0], o0[1]);
        *reinterpret_cast<__half2*>(g_AOf + r1 + e0) = __floats2half2_rn(o0[2], o0[3]);
        *reinterpret_cast<__half2*>(g_AOf + r0 + e1) = __floats2half2_rn(o1[0], o1[1]);
        *reinterpret_cast<__half2*>(g_AOf + r1 + e1) = __floats2half2_rn(o1[2], o1[3]);
    }
}

// ---------------------------------------------------------------------------
extern "C" void kernel_launch(void* const* d_in, const int* in_sizes, int n_in,
                              void* d_out, int out_size)
{
    const float* h_opt = (const float*)d_in[0];
    const float* h_sar = (const float*)d_in[1];
    const float* Wq  = (const float*)d_in[2];  const float* bq  = (const float*)d_in[3];
    const float* Wk  = (const float*)d_in[4];  const float* bk  = (const float*)d_in[5];
    const float* Wv  = (const float*)d_in[6];  const float* bv  = (const float*)d_in[7];
    const float* Wo  = (const float*)d_in[8];  const float* bo  = (const float*)d_in[9];
    const float* Wp1 = (const float*)d_in[10]; const float* bp1 = (const float*)d_in[11];
    const float* Wp2 = (const float*)d_in[12]; const float* bp2 = (const float*)d_in[13];
    float* out = (float*)d_out;

    void *pQ, *pK, *pV, *pAO, *pAS, *pAOf, *pWh;
    cudaGetSymbolAddress(&pQ,  g_Qh);
    cudaGetSymbolAddress(&pK,  g_Kh);
    cudaGetSymbolAddress(&pV,  g_Vh);
    cudaGetSymbolAddress(&pAO, g_AOpt);
    cudaGetSymbolAddress(&pAS, g_ASar);
    cudaGetSymbolAddress(&pAOf, g_AOf);
    cudaGetSymbolAddress(&pWh, g_Wth);

    __half* Wth = (__half*)pWh;

    constexpr int SM_PIPE = 3 * G_STG;   // 98304
    cudaFuncSetAttribute(gemm_q,   cudaFuncAttributeMaxDynamicSharedMemorySize, SM_PIPE);
    cudaFuncSetAttribute(gemm_kv,  cudaFuncAttributeMaxDynamicSharedMemorySize, SM_PIPE);
    cudaFuncSetAttribute(gemm_mlp, cudaFuncAttributeMaxDynamicSharedMemorySize, SM_PIPE);
    cudaFuncSetAttribute(gemm_out, cudaFuncAttributeMaxDynamicSharedMemorySize, SM_PIPE);
    cudaFuncSetAttribute(attn_kernel, cudaFuncAttributeMaxDynamicSharedMemorySize, ATT_SMEM);

    static cudaStream_t s1 = nullptr;
    static cudaEvent_t evRoot = nullptr, evW = nullptr, evSar = nullptr, evM = nullptr;
    if (s1 == nullptr) {
        cudaStreamCreateWithFlags(&s1, cudaStreamNonBlocking);
        cudaEventCreateWithFlags(&evRoot, cudaEventDisableTiming);
        cudaEventCreateWithFlags(&evW,    cudaEventDisableTiming);
        cudaEventCreateWithFlags(&evSar,  cudaEventDisableTiming);
        cudaEventCreateWithFlags(&evM,    cudaEventDisableTiming);
    }

    dim3 blk(256);
    cudaStream_t s0 = 0;

    cudaEventRecord(evRoot, s0);
    cudaStreamWaitEvent(s1, evRoot, 0);

    // launch 1 (s0): opt gather
    gather_kernel<<<dim3(8, 9, 64), blk, 0, s0>>>(h_opt, (__half*)pAO);

    // launch 2 (s1): all weight transposes
    wsplit_all<<<dim3(16, 16, 5), blk, 0, s1>>>(Wq, Wk, Wv, Wo, Wp1, Wth);
    cudaEventRecord(evW, s1);

    // launch 3 (s1): sar gather
    gather_kernel<<<dim3(8, 9, 64), blk, 0, s1>>>(h_sar, (__half*)pAS);
    cudaEventRecord(evSar, s1);

    // launch 4 (s1): MLP GEMM (sar + Wp1 ready on s1)
    gemm_mlp<<<dim3(1, 288), blk, SM_PIPE, s1>>>((__half*)pAS, Wth + WOFF_P1,
        bp1, Wp2, bp2);
    cudaEventRecord(evM, s1);

    // launch 5 (s0): Q GEMM — overlaps sar gather + MLP on s1
    cudaStreamWaitEvent(s0, evW, 0);
    gemm_q<<<dim3(4, 288), blk, SM_PIPE, s0>>>((__half*)pAO, Wth + WOFF_Q,
        bq, (__half*)pQ);

    // launch 6 (s0): K/V GEMMs
    cudaStreamWaitEvent(s0, evSar, 0);
    gemm_kv<<<dim3(4, 288, 2), blk, SM_PIPE, s0>>>((__half*)pAS, Wth,
        bk, bv, (__half*)pK, (__half*)pV);

    // launch 7 (s0): attention (needs QKV on s0, PV via evM)
    cudaStreamWaitEvent(s0, evM, 0);
    attn_kernel<<<NSEQ_, 256, ATT_SMEM, s0>>>();

    // launch 8 (s0): output projection + fused scatter
    gemm_out<<<dim3(4, 288), blk, SM_PIPE, s0>>>((__half*)pAOf, Wth + WOFF_O, bo, out);
}